// round 7
// baseline (speedup 1.0000x reference)
#include <cuda_runtime.h>
#include <cuda_bf16.h>
#include <cuda_fp8.h>
#include <cstdint>

#define BATCH 2
#define SEQ 2048
#define DMODEL 2048
#define NHEAD 16
#define HDIM 128
#define MTOT (BATCH*SEQ)          // 4096
#define NTOK (MTOT*DMODEL)        // 8388608
#define NW   (DMODEL*DMODEL)      // 4194304

// ---------------- scratch (device globals: allocation-free) ----------------
__device__ alignas(16) __nv_bfloat16 g_xs_h[NTOK];
__device__ alignas(16) unsigned char g_xs_8[NTOK], g_xs_l8[NTOK];
__device__ alignas(16) __nv_bfloat16 g_wq_h[NW], g_wk_h[NW], g_wv_h[NW], g_wo_h[NW];
__device__ alignas(16) unsigned char g_wq_8[NW], g_wq_l8[NW];
__device__ alignas(16) unsigned char g_wk_8[NW], g_wk_l8[NW];
__device__ alignas(16) unsigned char g_wv_8[NW], g_wv_l8[NW];
__device__ alignas(16) unsigned char g_wo_8[NW], g_wo_l8[NW];
__device__ alignas(16) __nv_bfloat16 g_q_h[NTOK], g_q_l[NTOK];
__device__ alignas(16) __nv_bfloat16 g_k_h[NTOK], g_k_l[NTOK];
__device__ alignas(16) __nv_bfloat16 g_v_h[NTOK], g_v_l[NTOK];
__device__ alignas(16) __nv_bfloat16 g_vt_h[NTOK], g_vt_l[NTOK];
__device__ alignas(16) __nv_bfloat16 g_c_h[NTOK];
__device__ alignas(16) unsigned char g_c_8[NTOK], g_c_l8[NTOK];

// ---------------- helpers ----------------
__device__ __forceinline__ uint32_t smem_u32(const void* p) {
    uint32_t a;
    asm("{ .reg .u64 t; cvta.to.shared.u64 t, %1; cvt.u32.u64 %0, t; }" : "=r"(a) : "l"(p));
    return a;
}

__device__ __forceinline__ void mma_bf16(float* c, const uint32_t* a, const uint32_t* b)
{
    asm volatile(
        "mma.sync.aligned.m16n8k16.row.col.f32.bf16.bf16.f32 "
        "{%0,%1,%2,%3}, {%4,%5,%6,%7}, {%8,%9}, {%0,%1,%2,%3};\n"
        : "+f"(c[0]), "+f"(c[1]), "+f"(c[2]), "+f"(c[3])
        : "r"(a[0]), "r"(a[1]), "r"(a[2]), "r"(a[3]), "r"(b[0]), "r"(b[1]));
}

__device__ __forceinline__ void mma_e4m3(float* c, const uint32_t* a, const uint32_t* b)
{
    asm volatile(
        "mma.sync.aligned.m16n8k32.row.col.f32.e4m3.e4m3.f32 "
        "{%0,%1,%2,%3}, {%4,%5,%6,%7}, {%8,%9}, {%0,%1,%2,%3};\n"
        : "+f"(c[0]), "+f"(c[1]), "+f"(c[2]), "+f"(c[3])
        : "r"(a[0]), "r"(a[1]), "r"(a[2]), "r"(a[3]), "r"(b[0]), "r"(b[1]));
}

__device__ __forceinline__ uint32_t pack_split(float x, float y, uint32_t& lo_out)
{
    __nv_bfloat16 hx = __float2bfloat16(x);
    __nv_bfloat16 hy = __float2bfloat16(y);
    __nv_bfloat16 lx = __float2bfloat16(x - __bfloat162float(hx));
    __nv_bfloat16 ly = __float2bfloat16(y - __bfloat162float(hy));
    __nv_bfloat162 h2 = __halves2bfloat162(hx, hy);
    __nv_bfloat162 l2 = __halves2bfloat162(lx, ly);
    lo_out = *(uint32_t*)&l2;
    return *(uint32_t*)&h2;
}

__device__ __forceinline__ uint16_t cvt2_e4m3(float x, float y)
{
    return (uint16_t)__nv_cvt_float2_to_fp8x2(make_float2(x, y), __NV_SATFINITE, __NV_E4M3);
}

// cp.async primitives
__device__ __forceinline__ void cp16(uint32_t dst, const void* src) {
    asm volatile("cp.async.cg.shared.global [%0], [%1], 16;" :: "r"(dst), "l"(src));
}
__device__ __forceinline__ void cp_commit() {
    asm volatile("cp.async.commit_group;" ::: "memory");
}
template<int N> __device__ __forceinline__ void cp_wait() {
    asm volatile("cp.async.wait_group %0;" :: "n"(N) : "memory");
}

// ---------------- fp32 -> (bf16 hi, fp8 full, fp8 lo-scaled) split ----------------
__global__ void split3_kernel(const float4* __restrict__ src,
                              uint2* __restrict__ hi,
                              uint32_t* __restrict__ f8,
                              uint32_t* __restrict__ l8,
                              int n4, float sa, float sl)
{
    int i = blockIdx.x * blockDim.x + threadIdx.x;
    if (i >= n4) return;
    float4 v = src[i];
    __nv_bfloat16 h0 = __float2bfloat16(v.x);
    __nv_bfloat16 h1 = __float2bfloat16(v.y);
    __nv_bfloat16 h2 = __float2bfloat16(v.z);
    __nv_bfloat16 h3 = __float2bfloat16(v.w);
    float l0 = v.x - __bfloat162float(h0);
    float l1 = v.y - __bfloat162float(h1);
    float l2 = v.z - __bfloat162float(h2);
    float l3 = v.w - __bfloat162float(h3);
    __nv_bfloat162 p0 = __halves2bfloat162(h0, h1);
    __nv_bfloat162 p1 = __halves2bfloat162(h2, h3);
    hi[i] = make_uint2(*(uint32_t*)&p0, *(uint32_t*)&p1);
    f8[i] = (uint32_t)cvt2_e4m3(v.x*sa, v.y*sa) | ((uint32_t)cvt2_e4m3(v.z*sa, v.w*sa) << 16);
    l8[i] = (uint32_t)cvt2_e4m3(l0*sl, l1*sl) | ((uint32_t)cvt2_e4m3(l2*sl, l3*sl) << 16);
}

// ---------------- per-batch 2048x2048 bf16 transpose ----------------
__global__ void transpose_bf16(const __nv_bfloat16* __restrict__ in,
                               __nv_bfloat16* __restrict__ out)
{
    __shared__ __nv_bfloat16 tile[32][33];
    const int bx = blockIdx.x * 32;
    const int by = blockIdx.y * 32;
    const long boff = (long)blockIdx.z * 2048 * 2048;
    const int tx = threadIdx.x & 31;
    const int ty = threadIdx.x >> 5;
#pragma unroll
    for (int j = 0; j < 4; j++) {
        int sl = ty + j*8;
        tile[sl][tx] = in[boff + (long)(by + sl)*2048 + bx + tx];
    }
    __syncthreads();
#pragma unroll
    for (int j = 0; j < 4; j++) {
        int hl = ty + j*8;
        out[boff + (long)(bx + hl)*2048 + by + tx] = tile[tx][hl];
    }
}

// ---------------------------------------------------------------------------
// bf16 hh + fp8 cross-term GEMM, 3-stage cp.async pipeline.
// C = (Ah+Al)(Bh+Bl)^T ; hh via bf16 k16 mma, (ah*bl + al*bh) via e4m3 k32 mma
// into a second accumulator, descaled by 2^-(sA+sB+9) in the epilogue.
// BM=BN=128, BK=32, 256 threads, warp tile 64x32.
// ---------------------------------------------------------------------------
#define GBM 128
#define GBN 128
#define GBK 32
// stage layout (bytes): bf16 pitch 80B (20 words), fp8 pitch 48B (12 words)
#define OF_AH  0
#define OF_BH  10240
#define OF_A8  20480
#define OF_AL8 26624
#define OF_B8  32768
#define OF_BL8 38912
#define STAGE_BYTES 45056
#define NSTAGE 3
#define GEMM_SMEM (NSTAGE*STAGE_BYTES)    // 135168

__device__ __forceinline__ void issue_tile(uint32_t sb,
    const __nv_bfloat16* __restrict__ Ah, const unsigned char* __restrict__ A8,
    const unsigned char* __restrict__ AL8,
    const __nv_bfloat16* __restrict__ Bh, const unsigned char* __restrict__ B8,
    const unsigned char* __restrict__ BL8,
    int m0, int n0, int K, int kofs, int tid)
{
#pragma unroll
    for (int i = 0; i < 2; i++) {
        int idx = tid + 256*i;
        int r = idx >> 2, c = idx & 3;
        cp16(sb + OF_AH + r*80 + c*16, Ah + (long)(m0 + r)*K + kofs + c*8);
        cp16(sb + OF_BH + r*80 + c*16, Bh + (long)(n0 + r)*K + kofs + c*8);
    }
    {
        int r = tid >> 1, c = tid & 1;
        long ga = (long)(m0 + r)*K + kofs + c*16;
        long gb = (long)(n0 + r)*K + kofs + c*16;
        uint32_t so = r*48 + c*16;
        cp16(sb + OF_A8  + so, A8  + ga);
        cp16(sb + OF_AL8 + so, AL8 + ga);
        cp16(sb + OF_B8  + so, B8  + gb);
        cp16(sb + OF_BL8 + so, BL8 + gb);
    }
}

template<bool SPLIT_OUT>
__global__ __launch_bounds__(256, 1)
void gemm_f8(const __nv_bfloat16* __restrict__ Agh, const unsigned char* __restrict__ Ag8,
             const unsigned char* __restrict__ Agl8,
             const __nv_bfloat16* __restrict__ Bgh, const unsigned char* __restrict__ Bg8,
             const unsigned char* __restrict__ Bgl8,
             float* __restrict__ Cf,
             __nv_bfloat16* __restrict__ Ch, __nv_bfloat16* __restrict__ Cl,
             const float* __restrict__ bias, float descale, int M, int N, int K)
{
    extern __shared__ __align__(16) char gsm[];
    const uint32_t smb = smem_u32(gsm);

    const int tid  = threadIdx.x;
    const int lane = tid & 31;
    const int wid  = tid >> 5;
    const int wm   = wid & 1;
    const int wn   = wid >> 1;
    const int g    = lane >> 2;
    const int t    = lane & 3;

    const int m0 = blockIdx.y * GBM;
    const int n0 = blockIdx.x * GBN;

    float acc[4][4][4];    // hh
    float acc2[4][4][4];   // cross (scaled by 2^(sA+sB+9))
#pragma unroll
    for (int mf = 0; mf < 4; mf++)
#pragma unroll
        for (int nf = 0; nf < 4; nf++)
#pragma unroll
            for (int c = 0; c < 4; c++) { acc[mf][nf][c] = 0.f; acc2[mf][nf][c] = 0.f; }

    const int nk = K / GBK;   // 64

    issue_tile(smb,               Agh, Ag8, Agl8, Bgh, Bg8, Bgl8, m0, n0, K, 0,   tid);
    cp_commit();
    issue_tile(smb + STAGE_BYTES, Agh, Ag8, Agl8, Bgh, Bg8, Bgl8, m0, n0, K, GBK, tid);
    cp_commit();

    for (int kt = 0; kt < nk; kt++) {
        cp_wait<1>();
        __syncthreads();

        if (kt + 2 < nk)
            issue_tile(smb + ((kt+2)%NSTAGE)*STAGE_BYTES,
                       Agh, Ag8, Agl8, Bgh, Bg8, Bgl8, m0, n0, K, (kt+2)*GBK, tid);
        cp_commit();

        const char* sbase = gsm + (kt % NSTAGE)*STAGE_BYTES;
        const uint32_t* AH32  = (const uint32_t*)(sbase + OF_AH);
        const uint32_t* BH32  = (const uint32_t*)(sbase + OF_BH);
        const uint32_t* A832  = (const uint32_t*)(sbase + OF_A8);
        const uint32_t* AL832 = (const uint32_t*)(sbase + OF_AL8);
        const uint32_t* B832  = (const uint32_t*)(sbase + OF_B8);
        const uint32_t* BL832 = (const uint32_t*)(sbase + OF_BL8);

        // ---- hh pass: bf16 k16 x2 ----
#pragma unroll
        for (int ks = 0; ks < 2; ks++) {
            const int kw = ks*8 + t;
            uint32_t ah[4][4], bh[4][2];
#pragma unroll
            for (int mf = 0; mf < 4; mf++) {
                int r0 = (wm*64 + mf*16 + g) * 20;
                int r1 = r0 + 8*20;
                ah[mf][0] = AH32[r0 + kw];     ah[mf][1] = AH32[r1 + kw];
                ah[mf][2] = AH32[r0 + kw + 4]; ah[mf][3] = AH32[r1 + kw + 4];
            }
#pragma unroll
            for (int nf = 0; nf < 4; nf++) {
                int rb = (wn*32 + nf*8 + g) * 20;
                bh[nf][0] = BH32[rb + kw];  bh[nf][1] = BH32[rb + kw + 4];
            }
#pragma unroll
            for (int mf = 0; mf < 4; mf++)
#pragma unroll
                for (int nf = 0; nf < 4; nf++)
                    mma_bf16(acc[mf][nf], ah[mf], bh[nf]);
        }

        // ---- cross pass: e4m3 k32, a8*bl8 + al8*b8 ----
        {
            uint32_t a8[4][4], al8[4][4], b8[4][2], bl8[4][2];
#pragma unroll
            for (int mf = 0; mf < 4; mf++) {
                int r0 = (wm*64 + mf*16 + g) * 12;
                int r1 = r0 + 8*12;
                a8[mf][0]  = A832[r0 + t];      a8[mf][1]  = A832[r1 + t];
                a8[mf][2]  = A832[r0 + t + 4];  a8[mf][3]  = A832[r1 + t + 4];
                al8[mf][0] = AL832[r0 + t];     al8[mf][1] = AL832[r1 + t];
                al8[mf][2] = AL832[r0 + t + 4]; al8[mf][3] = AL832[r1 + t + 4];
            }
#pragma unroll
            for (int nf = 0; nf < 4; nf++) {
                int rb = (wn*32 + nf*8 + g) * 12;
                b8[nf][0]  = B832[rb + t];   b8[nf][1]  = B832[rb + t + 4];
                bl8[nf][0] = BL832[rb + t];  bl8[nf][1] = BL832[rb + t + 4];
            }
#pragma unroll
            for (int mf = 0; mf < 4; mf++)
#pragma unroll
                for (int nf = 0; nf < 4; nf++)
                    mma_e4m3(acc2[mf][nf], a8[mf], bl8[nf]);
#pragma unroll
            for (int mf = 0; mf < 4; mf++)
#pragma unroll
                for (int nf = 0; nf < 4; nf++)
                    mma_e4m3(acc2[mf][nf], al8[mf], b8[nf]);
        }
        __syncthreads();
    }

    // epilogue: fold descaled cross terms, then write
#pragma unroll
    for (int nf = 0; nf < 4; nf++) {
        int col = n0 + wn*32 + nf*8 + 2*t;
        float b0 = 0.f, b1 = 0.f;
        if (!SPLIT_OUT && bias) { b0 = bias[col]; b1 = bias[col + 1]; }
#pragma unroll
        for (int mf = 0; mf < 4; mf++) {
            int row = m0 + wm*64 + mf*16 + g;
            float v0 = acc[mf][nf][0] + acc2[mf][nf][0]*descale;
            float v1 = acc[mf][nf][1] + acc2[mf][nf][1]*descale;
            float v2 = acc[mf][nf][2] + acc2[mf][nf][2]*descale;
            float v3 = acc[mf][nf][3] + acc2[mf][nf][3]*descale;
            if (SPLIT_OUT) {
                uint32_t l0, l1;
                uint32_t h0 = pack_split(v0, v1, l0);
                uint32_t h1 = pack_split(v2, v3, l1);
                *(uint32_t*)(Ch + (long)row*N + col)     = h0;
                *(uint32_t*)(Cl + (long)row*N + col)     = l0;
                *(uint32_t*)(Ch + (long)(row+8)*N + col) = h1;
                *(uint32_t*)(Cl + (long)(row+8)*N + col) = l1;
            } else {
                *(float2*)(Cf + (long)row*N + col)     = make_float2(v0 + b0, v1 + b1);
                *(float2*)(Cf + (long)(row+8)*N + col) = make_float2(v2 + b0, v3 + b1);
            }
        }
    }
}

// ---------------------------------------------------------------------------
// Tensor-core causal flash attention, bf16x3 (R6 design; epilogue now also
// emits fp8 operands for the WO GEMM).
// ---------------------------------------------------------------------------
#define AP 136
#define VP 72
#define ATTN_SMEM ((4*64*AP + 2*128*VP)*2)   // 106496 bytes

__global__ __launch_bounds__(128)
void attn_mma(const __nv_bfloat16* __restrict__ Qh, const __nv_bfloat16* __restrict__ Ql,
              const __nv_bfloat16* __restrict__ Kh, const __nv_bfloat16* __restrict__ Kl,
              const __nv_bfloat16* __restrict__ Vth, const __nv_bfloat16* __restrict__ Vtl,
              __nv_bfloat16* __restrict__ Ch, unsigned char* __restrict__ C8,
              unsigned char* __restrict__ Cl8)
{
    extern __shared__ __nv_bfloat16 sm[];
    __nv_bfloat16* sQh = sm;
    __nv_bfloat16* sQl = sQh + 64*AP;
    __nv_bfloat16* sKh = sQl + 64*AP;
    __nv_bfloat16* sKl = sKh + 64*AP;
    __nv_bfloat16* sVh = sKl + 64*AP;
    __nv_bfloat16* sVl = sVh + 128*VP;

    const int tid  = threadIdx.x;
    const int lane = tid & 31;
    const int wid  = tid >> 5;
    const int g    = lane >> 2;
    const int t    = lane & 3;

    const int qt = gridDim.x - 1 - blockIdx.x;   // LPT ordering
    const int h  = blockIdx.y;
    const int b  = blockIdx.z;
    const int q0 = qt * 64;

    const long qbase = ((long)(b*SEQ + q0))*DMODEL + h*HDIM;
#pragma unroll
    for (int i = 0; i < 8; i++) {
        int u = tid + 128*i;
        int r = u >> 4, c = (u & 15)*8;
        *(uint4*)(sQh + r*AP + c) = *(const uint4*)(Qh + qbase + (long)r*DMODEL + c);
        *(uint4*)(sQl + r*AP + c) = *(const uint4*)(Ql + qbase + (long)r*DMODEL + c);
    }

    float accO[16][4];
#pragma unroll
    for (int nb = 0; nb < 16; nb++)
#pragma unroll
        for (int c = 0; c < 4; c++) accO[nb][c] = 0.f;
    float m2[2] = {-1e30f, -1e30f};
    float lsum[2] = {0.f, 0.f};

    const float SC2 = 0.08838834764831845f * 1.4426950408889634f;
    const long vtbase = ((long)((b*NHEAD + h)*HDIM))*SEQ;

    for (int kt = 0; kt <= qt; kt++) {
        const int k0 = kt * 64;
        const long kbase = ((long)(b*SEQ + k0))*DMODEL + h*HDIM;
#pragma unroll
        for (int i = 0; i < 8; i++) {
            int u = tid + 128*i;
            int r = u >> 4, c = (u & 15)*8;
            *(uint4*)(sKh + r*AP + c) = *(const uint4*)(Kh + kbase + (long)r*DMODEL + c);
            *(uint4*)(sKl + r*AP + c) = *(const uint4*)(Kl + kbase + (long)r*DMODEL + c);
        }
#pragma unroll
        for (int i = 0; i < 8; i++) {
            int u = tid + 128*i;
            int d = u >> 3, c = (u & 7)*8;
            *(uint4*)(sVh + d*VP + c) = *(const uint4*)(Vth + vtbase + (long)d*SEQ + k0 + c);
            *(uint4*)(sVl + d*VP + c) = *(const uint4*)(Vtl + vtbase + (long)d*SEQ + k0 + c);
        }
        __syncthreads();

        float s[8][4];
#pragma unroll
        for (int nb = 0; nb < 8; nb++)
#pragma unroll
            for (int c = 0; c < 4; c++) s[nb][c] = 0.f;

        const uint32_t* Qh32 = (const uint32_t*)sQh;
        const uint32_t* Ql32 = (const uint32_t*)sQl;
        const uint32_t* Kh32 = (const uint32_t*)sKh;
        const uint32_t* Kl32 = (const uint32_t*)sKl;
        const int rq = wid*16 + g;
#pragma unroll
        for (int kc = 0; kc < 8; kc++) {
            int w0 = rq*(AP/2) + kc*8 + t;
            int w1 = w0 + 8*(AP/2);
            uint32_t ah[4] = {Qh32[w0], Qh32[w1], Qh32[w0+4], Qh32[w1+4]};
            uint32_t al[4] = {Ql32[w0], Ql32[w1], Ql32[w0+4], Ql32[w1+4]};
#pragma unroll
            for (int nb = 0; nb < 8; nb++) {
                int wb = (nb*8 + g)*(AP/2) + kc*8 + t;
                uint32_t bh[2] = {Kh32[wb], Kh32[wb+4]};
                uint32_t bl[2] = {Kl32[wb], Kl32[wb+4]};
                mma_bf16(s[nb], ah, bh);
                mma_bf16(s[nb], ah, bl);
                mma_bf16(s[nb], al, bh);
            }
        }

        if (kt == qt) {
            const int r0 = wid*16 + g, r1 = r0 + 8;
#pragma unroll
            for (int nb = 0; nb < 8; nb++) {
                int c0 = nb*8 + 2*t, c1 = c0 + 1;
                if (c0 > r0) s[nb][0] = -1e30f;
                if (c1 > r0) s[nb][1] = -1e30f;
                if (c0 > r1) s[nb][2] = -1e30f;
                if (c1 > r1) s[nb][3] = -1e30f;
            }
        }

        float mx0 = -1e30f, mx1 = -1e30f;
#pragma unroll
        for (int nb = 0; nb < 8; nb++) {
            mx0 = fmaxf(mx0, fmaxf(s[nb][0], s[nb][1]));
            mx1 = fmaxf(mx1, fmaxf(s[nb][2], s[nb][3]));
        }
        mx0 *= SC2; mx1 *= SC2;
#pragma unroll
        for (int off = 1; off <= 2; off <<= 1) {
            mx0 = fmaxf(mx0, __shfl_xor_sync(0xffffffffu, mx0, off));
            mx1 = fmaxf(mx1, __shfl_xor_sync(0xffffffffu, mx1, off));
        }
        float mn0 = fmaxf(m2[0], mx0), mn1 = fmaxf(m2[1], mx1);
        float corr0 = exp2f(m2[0] - mn0), corr1 = exp2f(m2[1] - mn1);
        float sum0 = 0.f, sum1 = 0.f;
#pragma unroll
        for (int nb = 0; nb < 8; nb++) {
            s[nb][0] = exp2f(s[nb][0]*SC2 - mn0);
            s[nb][1] = exp2f(s[nb][1]*SC2 - mn0);
            s[nb][2] = exp2f(s[nb][2]*SC2 - mn1);
            s[nb][3] = exp2f(s[nb][3]*SC2 - mn1);
            sum0 += s[nb][0] + s[nb][1];
            sum1 += s[nb][2] + s[nb][3];
        }
#pragma unroll
        for (int off = 1; off <= 2; off <<= 1) {
            sum0 += __shfl_xor_sync(0xffffffffu, sum0, off);
            sum1 += __shfl_xor_sync(0xffffffffu, sum1, off);
        }
        lsum[0] = lsum[0]*corr0 + sum0;
        lsum[1] = lsum[1]*corr1 + sum1;
        m2[0] = mn0; m2[1] = mn1;
#pragma unroll
        for (int nb = 0; nb < 16; nb++) {
            accO[nb][0] *= corr0; accO[nb][1] *= corr0;
            accO[nb][2] *= corr1; accO[nb][3] *= corr1;
        }

        uint32_t pah[4][4], pal[4][4];
#pragma unroll
        for (int kc = 0; kc < 4; kc++) {
            pah[kc][0] = pack_split(s[2*kc][0],   s[2*kc][1],   pal[kc][0]);
            pah[kc][1] = pack_split(s[2*kc][2],   s[2*kc][3],   pal[kc][1]);
            pah[kc][2] = pack_split(s[2*kc+1][0], s[2*kc+1][1], pal[kc][2]);
            pah[kc][3] = pack_split(s[2*kc+1][2], s[2*kc+1][3], pal[kc][3]);
        }

        const uint32_t* Vh32 = (const uint32_t*)sVh;
        const uint32_t* Vl32 = (const uint32_t*)sVl;
#pragma unroll
        for (int kc = 0; kc < 4; kc++) {
#pragma unroll
            for (int nb = 0; nb < 16; nb++) {
                int wb = (nb*8 + g)*(VP/2) + kc*8 + t;
                uint32_t bh[2] = {Vh32[wb], Vh32[wb+4]};
                uint32_t bl[2] = {Vl32[wb], Vl32[wb+4]};
                mma_bf16(accO[nb], pah[kc], bh);
                mma_bf16(accO[nb], pah[kc], bl);
                mma_bf16(accO[nb], pal[kc], bh);
            }
        }
        __syncthreads();
    }

    // epilogue: normalize; write ctx as (bf16 hi, fp8 full, fp8 lo*2^9)
    const float inv0 = 1.f / lsum[0], inv1 = 1.f / lsum[1];
    const long obase = ((long)(b*SEQ + q0 + wid*16))*DMODEL + h*HDIM;
#pragma unroll
    for (int nb = 0; nb < 16; nb++) {
        int col = nb*8 + 2*t;
        float x0 = accO[nb][0]*inv0, x1 = accO[nb][1]*inv0;
        float x2 = accO[nb][2]*inv1, x3 = accO[nb][3]*inv1;
        __nv_bfloat16 h0 = __float2bfloat16(x0), h1 = __float2bfloat16(x1);
        __nv_bfloat16 h2 = __float2bfloat16(x2), h3 = __float2bfloat16(x3);
        float l0 = x0 - __bfloat162float(h0), l1 = x1 - __bfloat162float(h1);
        float l2 = x2 - __bfloat162float(h2), l3 = x3 - __bfloat162float(h3);
        __nv_bfloat162 p0 = __halves2bfloat162(h0, h1);
        __nv_bfloat162 p1 = __halves2bfloat162(h2, h3);
        long o0 = obase + (long)g*DMODEL + col;
        long o1 = obase + (long)(g+8)*DMODEL + col;
        *(uint32_t*)(Ch + o0) = *(uint32_t*)&p0;
        *(uint32_t*)(Ch + o1) = *(uint32_t*)&p1;
        *(uint16_t*)(C8  + o0) = cvt2_e4m3(x0, x1);
        *(uint16_t*)(C8  + o1) = cvt2_e4m3(x2, x3);
        *(uint16_t*)(Cl8 + o0) = cvt2_e4m3(l0*512.f, l1*512.f);
        *(uint16_t*)(Cl8 + o1) = cvt2_e4m3(l2*512.f, l3*512.f);
    }
}

// ---------------------------------------------------------------------------
// Host launcher
// ---------------------------------------------------------------------------
extern "C" void kernel_launch(void* const* d_in, const int* in_sizes, int n_in,
                              void* d_out, int out_size)
{
    const float* x  = (const float*)d_in[0];
    const float* wq = (const float*)d_in[1];
    const float* wk = (const float*)d_in[2];
    const float* wv = (const float*)d_in[3];
    const float* wo = (const float*)d_in[4];
    const float* bo = (const float*)d_in[5];
    float* out = (float*)d_out;

    __nv_bfloat16 *xsh, *wqh, *wkh, *wvh, *woh;
    unsigned char *xs8, *xsl8, *wq8, *wql8, *wk8, *wkl8, *wv8, *wvl8, *wo8, *wol8;
    __nv_bfloat16 *qh, *ql, *kh, *kl, *vh, *vl, *vth, *vtl, *ch;
    unsigned char *c8, *cl8;
    cudaGetSymbolAddress((void**)&xsh, g_xs_h);
    cudaGetSymbolAddress((void**)&xs8, g_xs_8);   cudaGetSymbolAddress((void**)&xsl8, g_xs_l8);
    cudaGetSymbolAddress((void**)&wqh, g_wq_h);   cudaGetSymbolAddress((void**)&wq8, g_wq_8);
    cudaGetSymbolAddress((void**)&wql8, g_wq_l8);
    cudaGetSymbolAddress((void**)&wkh, g_wk_h);   cudaGetSymbolAddress((void**)&wk8, g_wk_8);
    cudaGetSymbolAddress((void**)&wkl8, g_wk_l8);
    cudaGetSymbolAddress((void**)&wvh, g_wv_h);   cudaGetSymbolAddress((void**)&wv8, g_wv_8);
    cudaGetSymbolAddress((void**)&wvl8, g_wv_l8);
    cudaGetSymbolAddress((void**)&woh, g_wo_h);   cudaGetSymbolAddress((void**)&wo8, g_wo_8);
    cudaGetSymbolAddress((void**)&wol8, g_wo_l8);
    cudaGetSymbolAddress((void**)&qh, g_q_h);     cudaGetSymbolAddress((void**)&ql, g_q_l);
    cudaGetSymbolAddress((void**)&kh, g_k_h);     cudaGetSymbolAddress((void**)&kl, g_k_l);
    cudaGetSymbolAddress((void**)&vh, g_v_h);     cudaGetSymbolAddress((void**)&vl, g_v_l);
    cudaGetSymbolAddress((void**)&vth, g_vt_h);   cudaGetSymbolAddress((void**)&vtl, g_vt_l);
    cudaGetSymbolAddress((void**)&ch, g_c_h);
    cudaGetSymbolAddress((void**)&c8, g_c_8);     cudaGetSymbolAddress((void**)&cl8, g_c_l8);

    static bool configured = false;
    if (!configured) {
        cudaFuncSetAttribute(gemm_f8<true>,  cudaFuncAttributeMaxDynamicSharedMemorySize, GEMM_SMEM);
        cudaFuncSetAttribute(gemm_f8<false>, cudaFuncAttributeMaxDynamicSharedMemorySize, GEMM_SMEM);
        cudaFuncSetAttribute(attn_mma, cudaFuncAttributeMaxDynamicSharedMemorySize, ATTN_SMEM);
        configured = true;
    }

    // scales: x/ctx: sA=0 (x1), lo x2^9 (512); weights: sB=5 (x32), lo x2^14 (16384)
    // cross-term descale = 2^-(sA+sB+9) = 2^-14
    const float DS = 6.103515625e-05f;   // 2^-14

    // 1) split inputs
    split3_kernel<<<(NTOK/4 + 255)/256, 256>>>((const float4*)x, (uint2*)xsh,
                                               (uint32_t*)xs8, (uint32_t*)xsl8, NTOK/4, 1.f, 512.f);
    split3_kernel<<<(NW/4 + 255)/256, 256>>>((const float4*)wq, (uint2*)wqh,
                                             (uint32_t*)wq8, (uint32_t*)wql8, NW/4, 32.f, 16384.f);
    split3_kernel<<<(NW/4 + 255)/256, 256>>>((const float4*)wk, (uint2*)wkh,
                                             (uint32_t*)wk8, (uint32_t*)wkl8, NW/4, 32.f, 16384.f);
    split3_kernel<<<(NW/4 + 255)/256, 256>>>((const float4*)wv, (uint2*)wvh,
                                             (uint32_t*)wv8, (uint32_t*)wvl8, NW/4, 32.f, 16384.f);
    split3_kernel<<<(NW/4 + 255)/256, 256>>>((const float4*)wo, (uint2*)woh,
                                             (uint32_t*)wo8, (uint32_t*)wol8, NW/4, 32.f, 16384.f);

    // 2) QKV projections (split bf16 hi/lo outputs for attention)
    dim3 gg(DMODEL/GBN, MTOT/GBM);   // (16, 32)
    gemm_f8<true><<<gg, 256, GEMM_SMEM>>>(xsh, xs8, xsl8, wqh, wq8, wql8,
                                          nullptr, qh, ql, nullptr, DS, MTOT, DMODEL, DMODEL);
    gemm_f8<true><<<gg, 256, GEMM_SMEM>>>(xsh, xs8, xsl8, wkh, wk8, wkl8,
                                          nullptr, kh, kl, nullptr, DS, MTOT, DMODEL, DMODEL);
    gemm_f8<true><<<gg, 256, GEMM_SMEM>>>(xsh, xs8, xsl8, wvh, wv8, wvl8,
                                          nullptr, vh, vl, nullptr, DS, MTOT, DMODEL, DMODEL);

    // 3) V transpose (per batch 2048x2048), hi and lo
    transpose_bf16<<<dim3(64, 64, BATCH), 256>>>(vh, vth);
    transpose_bf16<<<dim3(64, 64, BATCH), 256>>>(vl, vtl);

    // 4) attention (emits ctx as bf16-hi + fp8 pair)
    attn_mma<<<dim3(SEQ/64, NHEAD, BATCH), 128, ATTN_SMEM>>>(qh, ql, kh, kl, vth, vtl, ch, c8, cl8);

    // 5) output projection (fp32 + bias)
    gemm_f8<false><<<gg, 256, GEMM_SMEM>>>(ch, c8, cl8, woh, wo8, wol8,
                                           out, nullptr, nullptr, bo, DS, MTOT, DMODEL, DMODEL);
}

// round 8
// speedup vs baseline: 1.2853x; 1.2853x over previous
#include <cuda_runtime.h>
#include <cuda_bf16.h>
#include <cstdint>

#define BATCH 2
#define SEQ 2048
#define DMODEL 2048
#define NHEAD 16
#define HDIM 128
#define MTOT (BATCH*SEQ)          // 4096
#define NTOK (MTOT*DMODEL)        // 8388608
#define NW   (DMODEL*DMODEL)      // 4194304

// ---------------- scratch (device globals: allocation-free) ----------------
__device__ alignas(16) __nv_bfloat16 g_xs_h[NTOK], g_xs_l[NTOK];
__device__ alignas(16) __nv_bfloat16 g_wq_h[NW],  g_wq_l[NW];
__device__ alignas(16) __nv_bfloat16 g_wk_h[NW],  g_wk_l[NW];
__device__ alignas(16) __nv_bfloat16 g_wv_h[NW],  g_wv_l[NW];
__device__ alignas(16) __nv_bfloat16 g_wo_h[NW],  g_wo_l[NW];
__device__ alignas(16) __nv_bfloat16 g_q_h[NTOK], g_q_l[NTOK];
__device__ alignas(16) __nv_bfloat16 g_k_h[NTOK], g_k_l[NTOK];
__device__ alignas(16) __nv_bfloat16 g_v_h[NTOK], g_v_l[NTOK];
__device__ alignas(16) __nv_bfloat16 g_vt_h[NTOK], g_vt_l[NTOK];
__device__ alignas(16) __nv_bfloat16 g_c_h[NTOK], g_c_l[NTOK];

// ---------------- helpers ----------------
__device__ __forceinline__ uint32_t smem_u32(const void* p) {
    uint32_t a;
    asm("{ .reg .u64 t; cvta.to.shared.u64 t, %1; cvt.u32.u64 %0, t; }" : "=r"(a) : "l"(p));
    return a;
}

__device__ __forceinline__ void mma_bf16(float* c, const uint32_t* a, const uint32_t* b)
{
    asm volatile(
        "mma.sync.aligned.m16n8k16.row.col.f32.bf16.bf16.f32 "
        "{%0,%1,%2,%3}, {%4,%5,%6,%7}, {%8,%9}, {%0,%1,%2,%3};\n"
        : "+f"(c[0]), "+f"(c[1]), "+f"(c[2]), "+f"(c[3])
        : "r"(a[0]), "r"(a[1]), "r"(a[2]), "r"(a[3]), "r"(b[0]), "r"(b[1]));
}

__device__ __forceinline__ uint32_t pack_split(float x, float y, uint32_t& lo_out)
{
    __nv_bfloat16 hx = __float2bfloat16(x);
    __nv_bfloat16 hy = __float2bfloat16(y);
    __nv_bfloat16 lx = __float2bfloat16(x - __bfloat162float(hx));
    __nv_bfloat16 ly = __float2bfloat16(y - __bfloat162float(hy));
    __nv_bfloat162 h2 = __halves2bfloat162(hx, hy);
    __nv_bfloat162 l2 = __halves2bfloat162(lx, ly);
    lo_out = *(uint32_t*)&l2;
    return *(uint32_t*)&h2;
}

// cp.async primitives
__device__ __forceinline__ void cp16(uint32_t dst, const void* src) {
    asm volatile("cp.async.cg.shared.global [%0], [%1], 16;" :: "r"(dst), "l"(src));
}
__device__ __forceinline__ void cp_commit() {
    asm volatile("cp.async.commit_group;" ::: "memory");
}
template<int N> __device__ __forceinline__ void cp_wait() {
    asm volatile("cp.async.wait_group %0;" :: "n"(N) : "memory");
}

// ---------------- fp32 -> bf16 hi/lo split ----------------
__global__ void split_kernel(const float4* __restrict__ src,
                             uint2* __restrict__ hi, uint2* __restrict__ lo, int n4)
{
    int i = blockIdx.x * blockDim.x + threadIdx.x;
    if (i >= n4) return;
    float4 v = src[i];
    uint32_t l0, l1;
    uint32_t h0 = pack_split(v.x, v.y, l0);
    uint32_t h1 = pack_split(v.z, v.w, l1);
    hi[i] = make_uint2(h0, h1);
    lo[i] = make_uint2(l0, l1);
}

// ---------------- per-batch 2048x2048 bf16 transpose ----------------
__global__ void transpose_bf16(const __nv_bfloat16* __restrict__ in,
                               __nv_bfloat16* __restrict__ out)
{
    __shared__ __nv_bfloat16 tile[32][33];
    const int bx = blockIdx.x * 32;
    const int by = blockIdx.y * 32;
    const long boff = (long)blockIdx.z * 2048 * 2048;
    const int tx = threadIdx.x & 31;
    const int ty = threadIdx.x >> 5;
#pragma unroll
    for (int j = 0; j < 4; j++) {
        int sl = ty + j*8;
        tile[sl][tx] = in[boff + (long)(by + sl)*2048 + bx + tx];
    }
    __syncthreads();
#pragma unroll
    for (int j = 0; j < 4; j++) {
        int hl = ty + j*8;
        out[boff + (long)(bx + hl)*2048 + by + tx] = tile[tx][hl];
    }
}

// ---------------------------------------------------------------------------
// bf16x3 GEMM, BM=64 x BN=128, 128 threads, 3-stage cp.async, 2 CTAs/SM.
// Supports fused QKV: B/C selected by blockIdx.x>>4 (16 n-blocks per output).
// ---------------------------------------------------------------------------
#define G2BK 32
#define S_AH 0
#define S_AL 5120
#define S_BH 10240
#define S_BL 20480
#define STAGE2 30720
#define NST 3
#define GEMM_SMEM (NST*STAGE2)     // 92160

struct GemmArgs {
    const __nv_bfloat16 *Ah, *Al;
    const __nv_bfloat16 *Bh0, *Bl0, *Bh1, *Bl1, *Bh2, *Bl2;
    float* Cf;
    __nv_bfloat16 *Ch0, *Cl0, *Ch1, *Cl1, *Ch2, *Cl2;
    const float* bias;
};

__device__ __forceinline__ void issue_tile2(uint32_t sb,
    const __nv_bfloat16* __restrict__ Ah, const __nv_bfloat16* __restrict__ Al,
    const __nv_bfloat16* __restrict__ Bh, const __nv_bfloat16* __restrict__ Bl,
    int m0, int n0, int kofs, int tid)
{
#pragma unroll
    for (int i = 0; i < 2; i++) {
        int idx = tid + 128*i;
        int r = idx >> 2, c = idx & 3;
        uint32_t so = r*80 + c*16;
        long ga = (long)(m0 + r)*DMODEL + kofs + c*8;
        cp16(sb + S_AH + so, Ah + ga);
        cp16(sb + S_AL + so, Al + ga);
    }
#pragma unroll
    for (int i = 0; i < 4; i++) {
        int idx = tid + 128*i;
        int r = idx >> 2, c = idx & 3;
        uint32_t so = r*80 + c*16;
        long gb = (long)(n0 + r)*DMODEL + kofs + c*8;
        cp16(sb + S_BH + so, Bh + gb);
        cp16(sb + S_BL + so, Bl + gb);
    }
}

template<bool SPLIT_OUT>
__global__ __launch_bounds__(128, 2)
void gemm2(GemmArgs a)
{
    extern __shared__ __align__(16) char gsm[];
    const uint32_t smb = smem_u32(gsm);

    const int tid  = threadIdx.x;
    const int lane = tid & 31;
    const int wid  = tid >> 5;       // 0..3 (n-split)
    const int g    = lane >> 2;
    const int t    = lane & 3;

    const int bsel = blockIdx.x >> 4;               // 0..2 for fused QKV, 0 for WO
    const int n0   = (blockIdx.x & 15) * 128;
    const int m0   = blockIdx.y * 64;

    const __nv_bfloat16* Bh = (bsel == 0) ? a.Bh0 : (bsel == 1) ? a.Bh1 : a.Bh2;
    const __nv_bfloat16* Bl = (bsel == 0) ? a.Bl0 : (bsel == 1) ? a.Bl1 : a.Bl2;

    float acc[4][4][4];
#pragma unroll
    for (int mf = 0; mf < 4; mf++)
#pragma unroll
        for (int nf = 0; nf < 4; nf++)
#pragma unroll
            for (int c = 0; c < 4; c++) acc[mf][nf][c] = 0.f;

    const int nk = DMODEL / G2BK;   // 64

    issue_tile2(smb,          a.Ah, a.Al, Bh, Bl, m0, n0, 0,    tid);
    cp_commit();
    issue_tile2(smb + STAGE2, a.Ah, a.Al, Bh, Bl, m0, n0, G2BK, tid);
    cp_commit();

    for (int kt = 0; kt < nk; kt++) {
        cp_wait<1>();
        __syncthreads();

        if (kt + 2 < nk)
            issue_tile2(smb + ((kt+2)%NST)*STAGE2,
                        a.Ah, a.Al, Bh, Bl, m0, n0, (kt+2)*G2BK, tid);
        cp_commit();

        const char* sbase = gsm + (kt % NST)*STAGE2;
        const uint32_t* AH32 = (const uint32_t*)(sbase + S_AH);
        const uint32_t* AL32 = (const uint32_t*)(sbase + S_AL);
        const uint32_t* BH32 = (const uint32_t*)(sbase + S_BH);
        const uint32_t* BL32 = (const uint32_t*)(sbase + S_BL);

#pragma unroll
        for (int ks = 0; ks < 2; ks++) {
            const int kw = ks*8 + t;
            uint32_t ah[4][4], al[4][4], bh[4][2], bl[4][2];
#pragma unroll
            for (int mf = 0; mf < 4; mf++) {
                int r0 = (mf*16 + g) * 20;
                int r1 = r0 + 8*20;
                ah[mf][0] = AH32[r0 + kw];     ah[mf][1] = AH32[r1 + kw];
                ah[mf][2] = AH32[r0 + kw + 4]; ah[mf][3] = AH32[r1 + kw + 4];
                al[mf][0] = AL32[r0 + kw];     al[mf][1] = AL32[r1 + kw];
                al[mf][2] = AL32[r0 + kw + 4]; al[mf][3] = AL32[r1 + kw + 4];
            }
#pragma unroll
            for (int nf = 0; nf < 4; nf++) {
                int rb = (wid*32 + nf*8 + g) * 20;
                bh[nf][0] = BH32[rb + kw];  bh[nf][1] = BH32[rb + kw + 4];
                bl[nf][0] = BL32[rb + kw];  bl[nf][1] = BL32[rb + kw + 4];
            }
#pragma unroll
            for (int mf = 0; mf < 4; mf++)
#pragma unroll
                for (int nf = 0; nf < 4; nf++)
                    mma_bf16(acc[mf][nf], ah[mf], bh[nf]);
#pragma unroll
            for (int mf = 0; mf < 4; mf++)
#pragma unroll
                for (int nf = 0; nf < 4; nf++)
                    mma_bf16(acc[mf][nf], ah[mf], bl[nf]);
#pragma unroll
            for (int mf = 0; mf < 4; mf++)
#pragma unroll
                for (int nf = 0; nf < 4; nf++)
                    mma_bf16(acc[mf][nf], al[mf], bh[nf]);
        }
        __syncthreads();
    }

    __nv_bfloat16* Ch = (bsel == 0) ? a.Ch0 : (bsel == 1) ? a.Ch1 : a.Ch2;
    __nv_bfloat16* Cl = (bsel == 0) ? a.Cl0 : (bsel == 1) ? a.Cl1 : a.Cl2;

#pragma unroll
    for (int nf = 0; nf < 4; nf++) {
        int col = n0 + wid*32 + nf*8 + 2*t;
        float b0 = 0.f, b1 = 0.f;
        if (!SPLIT_OUT && a.bias) { b0 = a.bias[col]; b1 = a.bias[col + 1]; }
#pragma unroll
        for (int mf = 0; mf < 4; mf++) {
            int row = m0 + mf*16 + g;
            if (SPLIT_OUT) {
                uint32_t l0, l1;
                uint32_t h0 = pack_split(acc[mf][nf][0], acc[mf][nf][1], l0);
                uint32_t h1 = pack_split(acc[mf][nf][2], acc[mf][nf][3], l1);
                *(uint32_t*)(Ch + (long)row*DMODEL + col)     = h0;
                *(uint32_t*)(Cl + (long)row*DMODEL + col)     = l0;
                *(uint32_t*)(Ch + (long)(row+8)*DMODEL + col) = h1;
                *(uint32_t*)(Cl + (long)(row+8)*DMODEL + col) = l1;
            } else {
                *(float2*)(a.Cf + (long)row*DMODEL + col)     = make_float2(acc[mf][nf][0]+b0, acc[mf][nf][1]+b1);
                *(float2*)(a.Cf + (long)(row+8)*DMODEL + col) = make_float2(acc[mf][nf][2]+b0, acc[mf][nf][3]+b1);
            }
        }
    }
}

// ---------------------------------------------------------------------------
// Tensor-core causal flash attention, bf16x3 (R6 design, LPT order).
// ---------------------------------------------------------------------------
#define AP 136
#define VP 72
#define ATTN_SMEM ((4*64*AP + 2*128*VP)*2)   // 106496 bytes

__global__ __launch_bounds__(128)
void attn_mma(const __nv_bfloat16* __restrict__ Qh, const __nv_bfloat16* __restrict__ Ql,
              const __nv_bfloat16* __restrict__ Kh, const __nv_bfloat16* __restrict__ Kl,
              const __nv_bfloat16* __restrict__ Vth, const __nv_bfloat16* __restrict__ Vtl,
              __nv_bfloat16* __restrict__ Ch, __nv_bfloat16* __restrict__ Cl)
{
    extern __shared__ __nv_bfloat16 sm[];
    __nv_bfloat16* sQh = sm;
    __nv_bfloat16* sQl = sQh + 64*AP;
    __nv_bfloat16* sKh = sQl + 64*AP;
    __nv_bfloat16* sKl = sKh + 64*AP;
    __nv_bfloat16* sVh = sKl + 64*AP;
    __nv_bfloat16* sVl = sVh + 128*VP;

    const int tid  = threadIdx.x;
    const int lane = tid & 31;
    const int wid  = tid >> 5;
    const int g    = lane >> 2;
    const int t    = lane & 3;

    const int qt = gridDim.x - 1 - blockIdx.x;   // LPT ordering
    const int h  = blockIdx.y;
    const int b  = blockIdx.z;
    const int q0 = qt * 64;

    const long qbase = ((long)(b*SEQ + q0))*DMODEL + h*HDIM;
#pragma unroll
    for (int i = 0; i < 8; i++) {
        int u = tid + 128*i;
        int r = u >> 4, c = (u & 15)*8;
        *(uint4*)(sQh + r*AP + c) = *(const uint4*)(Qh + qbase + (long)r*DMODEL + c);
        *(uint4*)(sQl + r*AP + c) = *(const uint4*)(Ql + qbase + (long)r*DMODEL + c);
    }

    float accO[16][4];
#pragma unroll
    for (int nb = 0; nb < 16; nb++)
#pragma unroll
        for (int c = 0; c < 4; c++) accO[nb][c] = 0.f;
    float m2[2] = {-1e30f, -1e30f};
    float lsum[2] = {0.f, 0.f};

    const float SC2 = 0.08838834764831845f * 1.4426950408889634f;
    const long vtbase = ((long)((b*NHEAD + h)*HDIM))*SEQ;

    for (int kt = 0; kt <= qt; kt++) {
        const int k0 = kt * 64;
        const long kbase = ((long)(b*SEQ + k0))*DMODEL + h*HDIM;
#pragma unroll
        for (int i = 0; i < 8; i++) {
            int u = tid + 128*i;
            int r = u >> 4, c = (u & 15)*8;
            *(uint4*)(sKh + r*AP + c) = *(const uint4*)(Kh + kbase + (long)r*DMODEL + c);
            *(uint4*)(sKl + r*AP + c) = *(const uint4*)(Kl + kbase + (long)r*DMODEL + c);
        }
#pragma unroll
        for (int i = 0; i < 8; i++) {
            int u = tid + 128*i;
            int d = u >> 3, c = (u & 7)*8;
            *(uint4*)(sVh + d*VP + c) = *(const uint4*)(Vth + vtbase + (long)d*SEQ + k0 + c);
            *(uint4*)(sVl + d*VP + c) = *(const uint4*)(Vtl + vtbase + (long)d*SEQ + k0 + c);
        }
        __syncthreads();

        float s[8][4];
#pragma unroll
        for (int nb = 0; nb < 8; nb++)
#pragma unroll
            for (int c = 0; c < 4; c++) s[nb][c] = 0.f;

        const uint32_t* Qh32 = (const uint32_t*)sQh;
        const uint32_t* Ql32 = (const uint32_t*)sQl;
        const uint32_t* Kh32 = (const uint32_t*)sKh;
        const uint32_t* Kl32 = (const uint32_t*)sKl;
        const int rq = wid*16 + g;
#pragma unroll
        for (int kc = 0; kc < 8; kc++) {
            int w0 = rq*(AP/2) + kc*8 + t;
            int w1 = w0 + 8*(AP/2);
            uint32_t ah[4] = {Qh32[w0], Qh32[w1], Qh32[w0+4], Qh32[w1+4]};
            uint32_t al[4] = {Ql32[w0], Ql32[w1], Ql32[w0+4], Ql32[w1+4]};
#pragma unroll
            for (int nb = 0; nb < 8; nb++) {
                int wb = (nb*8 + g)*(AP/2) + kc*8 + t;
                uint32_t bh[2] = {Kh32[wb], Kh32[wb+4]};
                uint32_t bl[2] = {Kl32[wb], Kl32[wb+4]};
                mma_bf16(s[nb], ah, bh);
                mma_bf16(s[nb], ah, bl);
                mma_bf16(s[nb], al, bh);
            }
        }

        if (kt == qt) {
            const int r0 = wid*16 + g, r1 = r0 + 8;
#pragma unroll
            for (int nb = 0; nb < 8; nb++) {
                int c0 = nb*8 + 2*t, c1 = c0 + 1;
                if (c0 > r0) s[nb][0] = -1e30f;
                if (c1 > r0) s[nb][1] = -1e30f;
                if (c0 > r1) s[nb][2] = -1e30f;
                if (c1 > r1) s[nb][3] = -1e30f;
            }
        }

        float mx0 = -1e30f, mx1 = -1e30f;
#pragma unroll
        for (int nb = 0; nb < 8; nb++) {
            mx0 = fmaxf(mx0, fmaxf(s[nb][0], s[nb][1]));
            mx1 = fmaxf(mx1, fmaxf(s[nb][2], s[nb][3]));
        }
        mx0 *= SC2; mx1 *= SC2;
#pragma unroll
        for (int off = 1; off <= 2; off <<= 1) {
            mx0 = fmaxf(mx0, __shfl_xor_sync(0xffffffffu, mx0, off));
            mx1 = fmaxf(mx1, __shfl_xor_sync(0xffffffffu, mx1, off));
        }
        float mn0 = fmaxf(m2[0], mx0), mn1 = fmaxf(m2[1], mx1);
        float corr0 = exp2f(m2[0] - mn0), corr1 = exp2f(m2[1] - mn1);
        float sum0 = 0.f, sum1 = 0.f;
#pragma unroll
        for (int nb = 0; nb < 8; nb++) {
            s[nb][0] = exp2f(s[nb][0]*SC2 - mn0);
            s[nb][1] = exp2f(s[nb][1]*SC2 - mn0);
            s[nb][2] = exp2f(s[nb][2]*SC2 - mn1);
            s[nb][3] = exp2f(s[nb][3]*SC2 - mn1);
            sum0 += s[nb][0] + s[nb][1];
            sum1 += s[nb][2] + s[nb][3];
        }
#pragma unroll
        for (int off = 1; off <= 2; off <<= 1) {
            sum0 += __shfl_xor_sync(0xffffffffu, sum0, off);
            sum1 += __shfl_xor_sync(0xffffffffu, sum1, off);
        }
        lsum[0] = lsum[0]*corr0 + sum0;
        lsum[1] = lsum[1]*corr1 + sum1;
        m2[0] = mn0; m2[1] = mn1;
#pragma unroll
        for (int nb = 0; nb < 16; nb++) {
            accO[nb][0] *= corr0; accO[nb][1] *= corr0;
            accO[nb][2] *= corr1; accO[nb][3] *= corr1;
        }

        uint32_t pah[4][4], pal[4][4];
#pragma unroll
        for (int kc = 0; kc < 4; kc++) {
            pah[kc][0] = pack_split(s[2*kc][0],   s[2*kc][1],   pal[kc][0]);
            pah[kc][1] = pack_split(s[2*kc][2],   s[2*kc][3],   pal[kc][1]);
            pah[kc][2] = pack_split(s[2*kc+1][0], s[2*kc+1][1], pal[kc][2]);
            pah[kc][3] = pack_split(s[2*kc+1][2], s[2*kc+1][3], pal[kc][3]);
        }

        const uint32_t* Vh32 = (const uint32_t*)sVh;
        const uint32_t* Vl32 = (const uint32_t*)sVl;
#pragma unroll
        for (int kc = 0; kc < 4; kc++) {
#pragma unroll
            for (int nb = 0; nb < 16; nb++) {
                int wb = (nb*8 + g)*(VP/2) + kc*8 + t;
                uint32_t bh[2] = {Vh32[wb], Vh32[wb+4]};
                uint32_t bl[2] = {Vl32[wb], Vl32[wb+4]};
                mma_bf16(accO[nb], pah[kc], bh);
                mma_bf16(accO[nb], pah[kc], bl);
                mma_bf16(accO[nb], pal[kc], bh);
            }
        }
        __syncthreads();
    }

    const float inv0 = 1.f / lsum[0], inv1 = 1.f / lsum[1];
    const long obase = ((long)(b*SEQ + q0 + wid*16))*DMODEL + h*HDIM;
#pragma unroll
    for (int nb = 0; nb < 16; nb++) {
        int col = nb*8 + 2*t;
        uint32_t l0, l1;
        uint32_t h0 = pack_split(accO[nb][0]*inv0, accO[nb][1]*inv0, l0);
        uint32_t h1 = pack_split(accO[nb][2]*inv1, accO[nb][3]*inv1, l1);
        *(uint32_t*)(Ch + obase + (long)g*DMODEL + col)     = h0;
        *(uint32_t*)(Cl + obase + (long)g*DMODEL + col)     = l0;
        *(uint32_t*)(Ch + obase + (long)(g+8)*DMODEL + col) = h1;
        *(uint32_t*)(Cl + obase + (long)(g+8)*DMODEL + col) = l1;
    }
}

// ---------------------------------------------------------------------------
// Host launcher
// ---------------------------------------------------------------------------
extern "C" void kernel_launch(void* const* d_in, const int* in_sizes, int n_in,
                              void* d_out, int out_size)
{
    const float* x  = (const float*)d_in[0];
    const float* wq = (const float*)d_in[1];
    const float* wk = (const float*)d_in[2];
    const float* wv = (const float*)d_in[3];
    const float* wo = (const float*)d_in[4];
    const float* bo = (const float*)d_in[5];
    float* out = (float*)d_out;

    __nv_bfloat16 *xs_h, *xs_l, *wqh, *wql, *wkh, *wkl, *wvh, *wvl, *woh, *wol;
    __nv_bfloat16 *qh, *ql, *kh, *kl, *vh, *vl, *vth, *vtl, *ch, *cl;
    cudaGetSymbolAddress((void**)&xs_h, g_xs_h); cudaGetSymbolAddress((void**)&xs_l, g_xs_l);
    cudaGetSymbolAddress((void**)&wqh, g_wq_h);  cudaGetSymbolAddress((void**)&wql, g_wq_l);
    cudaGetSymbolAddress((void**)&wkh, g_wk_h);  cudaGetSymbolAddress((void**)&wkl, g_wk_l);
    cudaGetSymbolAddress((void**)&wvh, g_wv_h);  cudaGetSymbolAddress((void**)&wvl, g_wv_l);
    cudaGetSymbolAddress((void**)&woh, g_wo_h);  cudaGetSymbolAddress((void**)&wol, g_wo_l);
    cudaGetSymbolAddress((void**)&qh, g_q_h);    cudaGetSymbolAddress((void**)&ql, g_q_l);
    cudaGetSymbolAddress((void**)&kh, g_k_h);    cudaGetSymbolAddress((void**)&kl, g_k_l);
    cudaGetSymbolAddress((void**)&vh, g_v_h);    cudaGetSymbolAddress((void**)&vl, g_v_l);
    cudaGetSymbolAddress((void**)&vth, g_vt_h);  cudaGetSymbolAddress((void**)&vtl, g_vt_l);
    cudaGetSymbolAddress((void**)&ch, g_c_h);    cudaGetSymbolAddress((void**)&cl, g_c_l);

    static bool configured = false;
    if (!configured) {
        cudaFuncSetAttribute(gemm2<true>,  cudaFuncAttributeMaxDynamicSharedMemorySize, GEMM_SMEM);
        cudaFuncSetAttribute(gemm2<false>, cudaFuncAttributeMaxDynamicSharedMemorySize, GEMM_SMEM);
        cudaFuncSetAttribute(attn_mma, cudaFuncAttributeMaxDynamicSharedMemorySize, ATTN_SMEM);
        configured = true;
    }

    // 1) split inputs
    split_kernel<<<(NTOK/4 + 255)/256, 256>>>((const float4*)x,  (uint2*)xs_h, (uint2*)xs_l, NTOK/4);
    split_kernel<<<(NW/4 + 255)/256, 256>>>((const float4*)wq, (uint2*)wqh, (uint2*)wql, NW/4);
    split_kernel<<<(NW/4 + 255)/256, 256>>>((const float4*)wk, (uint2*)wkh, (uint2*)wkl, NW/4);
    split_kernel<<<(NW/4 + 255)/256, 256>>>((const float4*)wv, (uint2*)wvh, (uint2*)wvl, NW/4);
    split_kernel<<<(NW/4 + 255)/256, 256>>>((const float4*)wo, (uint2*)woh, (uint2*)wol, NW/4);

    // 2) fused QKV projection: one launch, grid (48, 64)
    {
        GemmArgs a = {};
        a.Ah = xs_h; a.Al = xs_l;
        a.Bh0 = wqh; a.Bl0 = wql; a.Bh1 = wkh; a.Bl1 = wkl; a.Bh2 = wvh; a.Bl2 = wvl;
        a.Ch0 = qh;  a.Cl0 = ql;  a.Ch1 = kh;  a.Cl1 = kl;  a.Ch2 = vh;  a.Cl2 = vl;
        gemm2<true><<<dim3(48, MTOT/64), 128, GEMM_SMEM>>>(a);
    }

    // 3) V transpose (per batch 2048x2048), hi and lo
    transpose_bf16<<<dim3(64, 64, BATCH), 256>>>(vh, vth);
    transpose_bf16<<<dim3(64, 64, BATCH), 256>>>(vl, vtl);

    // 4) attention
    attn_mma<<<dim3(SEQ/64, NHEAD, BATCH), 128, ATTN_SMEM>>>(qh, ql, kh, kl, vth, vtl, ch, cl);

    // 5) output projection (fp32 + bias)
    {
        GemmArgs a = {};
        a.Ah = ch; a.Al = cl;
        a.Bh0 = woh; a.Bl0 = wol; a.Bh1 = woh; a.Bl1 = wol; a.Bh2 = woh; a.Bl2 = wol;
        a.Cf = out; a.bias = bo;
        gemm2<false><<<dim3(16, MTOT/64), 128, GEMM_SMEM>>>(a);
    }
}

// round 9
// speedup vs baseline: 1.3081x; 1.0177x over previous
#include <cuda_runtime.h>
#include <cuda_bf16.h>
#include <cstdint>

#define BATCH 2
#define SEQ 2048
#define DMODEL 2048
#define NHEAD 16
#define HDIM 128
#define MTOT (BATCH*SEQ)          // 4096
#define NTOK (MTOT*DMODEL)        // 8388608
#define NW   (DMODEL*DMODEL)      // 4194304

// ---------------- scratch (device globals: allocation-free) ----------------
__device__ alignas(16) __nv_bfloat16 g_xs_h[NTOK], g_xs_l[NTOK];
__device__ alignas(16) __nv_bfloat16 g_wq_h[NW],  g_wq_l[NW];
__device__ alignas(16) __nv_bfloat16 g_wk_h[NW],  g_wk_l[NW];
__device__ alignas(16) __nv_bfloat16 g_wv_h[NW],  g_wv_l[NW];
__device__ alignas(16) __nv_bfloat16 g_wo_h[NW],  g_wo_l[NW];
__device__ alignas(16) __nv_bfloat16 g_q_h[NTOK], g_q_l[NTOK];
__device__ alignas(16) __nv_bfloat16 g_k_h[NTOK], g_k_l[NTOK];
__device__ alignas(16) __nv_bfloat16 g_v_h[NTOK], g_v_l[NTOK];
__device__ alignas(16) __nv_bfloat16 g_vt_h[NTOK], g_vt_l[NTOK];
__device__ alignas(16) __nv_bfloat16 g_c_h[NTOK], g_c_l[NTOK];

// ---------------- helpers ----------------
__device__ __forceinline__ uint32_t smem_u32(const void* p) {
    uint32_t a;
    asm("{ .reg .u64 t; cvta.to.shared.u64 t, %1; cvt.u32.u64 %0, t; }" : "=r"(a) : "l"(p));
    return a;
}

__device__ __forceinline__ void mma_bf16(float* c, const uint32_t* a, const uint32_t* b)
{
    asm volatile(
        "mma.sync.aligned.m16n8k16.row.col.f32.bf16.bf16.f32 "
        "{%0,%1,%2,%3}, {%4,%5,%6,%7}, {%8,%9}, {%0,%1,%2,%3};\n"
        : "+f"(c[0]), "+f"(c[1]), "+f"(c[2]), "+f"(c[3])
        : "r"(a[0]), "r"(a[1]), "r"(a[2]), "r"(a[3]), "r"(b[0]), "r"(b[1]));
}

__device__ __forceinline__ uint32_t pack_split(float x, float y, uint32_t& lo_out)
{
    __nv_bfloat16 hx = __float2bfloat16(x);
    __nv_bfloat16 hy = __float2bfloat16(y);
    __nv_bfloat16 lx = __float2bfloat16(x - __bfloat162float(hx));
    __nv_bfloat16 ly = __float2bfloat16(y - __bfloat162float(hy));
    __nv_bfloat162 h2 = __halves2bfloat162(hx, hy);
    __nv_bfloat162 l2 = __halves2bfloat162(lx, ly);
    lo_out = *(uint32_t*)&l2;
    return *(uint32_t*)&h2;
}

// cp.async primitives
__device__ __forceinline__ void cp16(uint32_t dst, const void* src) {
    asm volatile("cp.async.cg.shared.global [%0], [%1], 16;" :: "r"(dst), "l"(src));
}
__device__ __forceinline__ void cp_commit() {
    asm volatile("cp.async.commit_group;" ::: "memory");
}
template<int N> __device__ __forceinline__ void cp_wait() {
    asm volatile("cp.async.wait_group %0;" :: "n"(N) : "memory");
}

// ---------------- fp32 -> bf16 hi/lo split ----------------
__global__ void split_kernel(const float4* __restrict__ src,
                             uint2* __restrict__ hi, uint2* __restrict__ lo, int n4)
{
    int i = blockIdx.x * blockDim.x + threadIdx.x;
    if (i >= n4) return;
    float4 v = src[i];
    uint32_t l0, l1;
    uint32_t h0 = pack_split(v.x, v.y, l0);
    uint32_t h1 = pack_split(v.z, v.w, l1);
    hi[i] = make_uint2(h0, h1);
    lo[i] = make_uint2(l0, l1);
}

// ---------------- per-batch 2048x2048 bf16 transpose (hi+lo fused) ----------
__global__ void transpose_bf16(const __nv_bfloat16* __restrict__ in_h,
                               __nv_bfloat16* __restrict__ out_h,
                               const __nv_bfloat16* __restrict__ in_l,
                               __nv_bfloat16* __restrict__ out_l)
{
    __shared__ __nv_bfloat16 tile[32][33];
    const int bx = blockIdx.x * 32;
    const int by = blockIdx.y * 32;
    const int b  = blockIdx.z & 1;
    const int sel = blockIdx.z >> 1;              // 0 = hi, 1 = lo
    const __nv_bfloat16* in  = sel ? in_l  : in_h;
    __nv_bfloat16*       out = sel ? out_l : out_h;
    const long boff = (long)b * 2048 * 2048;
    const int tx = threadIdx.x & 31;
    const int ty = threadIdx.x >> 5;
#pragma unroll
    for (int j = 0; j < 4; j++) {
        int sl = ty + j*8;
        tile[sl][tx] = in[boff + (long)(by + sl)*2048 + bx + tx];
    }
    __syncthreads();
#pragma unroll
    for (int j = 0; j < 4; j++) {
        int hl = ty + j*8;
        out[boff + (long)(bx + hl)*2048 + by + tx] = tile[tx][hl];
    }
}

// ---------------------------------------------------------------------------
// bf16x3 GEMM, BM=64 x BN=128, 128 threads, 2-stage cp.async, 3 CTAs/SM.
// Supports fused QKV: B/C selected by blockIdx.x>>4 (16 n-blocks per output).
// ---------------------------------------------------------------------------
#define G2BK 32
#define S_AH 0
#define S_AL 5120
#define S_BH 10240
#define S_BL 20480
#define STAGE2 30720
#define NST 2
#define GEMM_SMEM (NST*STAGE2)     // 61440 -> 3 CTAs/SM (184 KB)

struct GemmArgs {
    const __nv_bfloat16 *Ah, *Al;
    const __nv_bfloat16 *Bh0, *Bl0, *Bh1, *Bl1, *Bh2, *Bl2;
    float* Cf;
    __nv_bfloat16 *Ch0, *Cl0, *Ch1, *Cl1, *Ch2, *Cl2;
    const float* bias;
};

__device__ __forceinline__ void issue_tile2(uint32_t sb,
    const __nv_bfloat16* __restrict__ Ah, const __nv_bfloat16* __restrict__ Al,
    const __nv_bfloat16* __restrict__ Bh, const __nv_bfloat16* __restrict__ Bl,
    int m0, int n0, int kofs, int tid)
{
#pragma unroll
    for (int i = 0; i < 2; i++) {
        int idx = tid + 128*i;
        int r = idx >> 2, c = idx & 3;
        uint32_t so = r*80 + c*16;
        long ga = (long)(m0 + r)*DMODEL + kofs + c*8;
        cp16(sb + S_AH + so, Ah + ga);
        cp16(sb + S_AL + so, Al + ga);
    }
#pragma unroll
    for (int i = 0; i < 4; i++) {
        int idx = tid + 128*i;
        int r = idx >> 2, c = idx & 3;
        uint32_t so = r*80 + c*16;
        long gb = (long)(n0 + r)*DMODEL + kofs + c*8;
        cp16(sb + S_BH + so, Bh + gb);
        cp16(sb + S_BL + so, Bl + gb);
    }
}

template<bool SPLIT_OUT>
__global__ __launch_bounds__(128, 3)
void gemm2(GemmArgs a)
{
    extern __shared__ __align__(16) char gsm[];
    const uint32_t smb = smem_u32(gsm);

    const int tid  = threadIdx.x;
    const int lane = tid & 31;
    const int wid  = tid >> 5;       // 0..3 (n-split)
    const int g    = lane >> 2;
    const int t    = lane & 3;

    const int bsel = blockIdx.x >> 4;               // 0..2 for fused QKV, 0 for WO
    const int n0   = (blockIdx.x & 15) * 128;
    const int m0   = blockIdx.y * 64;

    const __nv_bfloat16* Bh = (bsel == 0) ? a.Bh0 : (bsel == 1) ? a.Bh1 : a.Bh2;
    const __nv_bfloat16* Bl = (bsel == 0) ? a.Bl0 : (bsel == 1) ? a.Bl1 : a.Bl2;

    float acc[4][4][4];
#pragma unroll
    for (int mf = 0; mf < 4; mf++)
#pragma unroll
        for (int nf = 0; nf < 4; nf++)
#pragma unroll
            for (int c = 0; c < 4; c++) acc[mf][nf][c] = 0.f;

    const int nk = DMODEL / G2BK;   // 64

    issue_tile2(smb,          a.Ah, a.Al, Bh, Bl, m0, n0, 0,    tid);
    cp_commit();
    issue_tile2(smb + STAGE2, a.Ah, a.Al, Bh, Bl, m0, n0, G2BK, tid);
    cp_commit();

    for (int kt = 0; kt < nk; kt++) {
        cp_wait<1>();
        __syncthreads();

        const char* sbase = gsm + (kt & 1)*STAGE2;
        const uint32_t* AH32 = (const uint32_t*)(sbase + S_AH);
        const uint32_t* AL32 = (const uint32_t*)(sbase + S_AL);
        const uint32_t* BH32 = (const uint32_t*)(sbase + S_BH);
        const uint32_t* BL32 = (const uint32_t*)(sbase + S_BL);

#pragma unroll
        for (int ks = 0; ks < 2; ks++) {
            const int kw = ks*8 + t;
            uint32_t ah[4][4], al[4][4], bh[4][2], bl[4][2];
#pragma unroll
            for (int mf = 0; mf < 4; mf++) {
                int r0 = (mf*16 + g) * 20;
                int r1 = r0 + 8*20;
                ah[mf][0] = AH32[r0 + kw];     ah[mf][1] = AH32[r1 + kw];
                ah[mf][2] = AH32[r0 + kw + 4]; ah[mf][3] = AH32[r1 + kw + 4];
                al[mf][0] = AL32[r0 + kw];     al[mf][1] = AL32[r1 + kw];
                al[mf][2] = AL32[r0 + kw + 4]; al[mf][3] = AL32[r1 + kw + 4];
            }
#pragma unroll
            for (int nf = 0; nf < 4; nf++) {
                int rb = (wid*32 + nf*8 + g) * 20;
                bh[nf][0] = BH32[rb + kw];  bh[nf][1] = BH32[rb + kw + 4];
                bl[nf][0] = BL32[rb + kw];  bl[nf][1] = BL32[rb + kw + 4];
            }
#pragma unroll
            for (int mf = 0; mf < 4; mf++)
#pragma unroll
                for (int nf = 0; nf < 4; nf++)
                    mma_bf16(acc[mf][nf], ah[mf], bh[nf]);
#pragma unroll
            for (int mf = 0; mf < 4; mf++)
#pragma unroll
                for (int nf = 0; nf < 4; nf++)
                    mma_bf16(acc[mf][nf], ah[mf], bl[nf]);
#pragma unroll
            for (int mf = 0; mf < 4; mf++)
#pragma unroll
                for (int nf = 0; nf < 4; nf++)
                    mma_bf16(acc[mf][nf], al[mf], bh[nf]);
        }
        __syncthreads();   // all warps done with buffer (kt&1)

        if (kt + 2 < nk)
            issue_tile2(smb + (kt & 1)*STAGE2,
                        a.Ah, a.Al, Bh, Bl, m0, n0, (kt+2)*G2BK, tid);
        cp_commit();       // unconditional: keeps group ids aligned
    }

    __nv_bfloat16* Ch = (bsel == 0) ? a.Ch0 : (bsel == 1) ? a.Ch1 : a.Ch2;
    __nv_bfloat16* Cl = (bsel == 0) ? a.Cl0 : (bsel == 1) ? a.Cl1 : a.Cl2;

#pragma unroll
    for (int nf = 0; nf < 4; nf++) {
        int col = n0 + wid*32 + nf*8 + 2*t;
        float b0 = 0.f, b1 = 0.f;
        if (!SPLIT_OUT && a.bias) { b0 = a.bias[col]; b1 = a.bias[col + 1]; }
#pragma unroll
        for (int mf = 0; mf < 4; mf++) {
            int row = m0 + mf*16 + g;
            if (SPLIT_OUT) {
                uint32_t l0, l1;
                uint32_t h0 = pack_split(acc[mf][nf][0], acc[mf][nf][1], l0);
                uint32_t h1 = pack_split(acc[mf][nf][2], acc[mf][nf][3], l1);
                *(uint32_t*)(Ch + (long)row*DMODEL + col)     = h0;
                *(uint32_t*)(Cl + (long)row*DMODEL + col)     = l0;
                *(uint32_t*)(Ch + (long)(row+8)*DMODEL + col) = h1;
                *(uint32_t*)(Cl + (long)(row+8)*DMODEL + col) = l1;
            } else {
                *(float2*)(a.Cf + (long)row*DMODEL + col)     = make_float2(acc[mf][nf][0]+b0, acc[mf][nf][1]+b1);
                *(float2*)(a.Cf + (long)(row+8)*DMODEL + col) = make_float2(acc[mf][nf][2]+b0, acc[mf][nf][3]+b1);
            }
        }
    }
}

// ---------------------------------------------------------------------------
// Tensor-core causal flash attention, bf16x3 (unchanged from R8).
// ---------------------------------------------------------------------------
#define AP 136
#define VP 72
#define ATTN_SMEM ((4*64*AP + 2*128*VP)*2)   // 106496 bytes

__global__ __launch_bounds__(128)
void attn_mma(const __nv_bfloat16* __restrict__ Qh, const __nv_bfloat16* __restrict__ Ql,
              const __nv_bfloat16* __restrict__ Kh, const __nv_bfloat16* __restrict__ Kl,
              const __nv_bfloat16* __restrict__ Vth, const __nv_bfloat16* __restrict__ Vtl,
              __nv_bfloat16* __restrict__ Ch, __nv_bfloat16* __restrict__ Cl)
{
    extern __shared__ __nv_bfloat16 sm[];
    __nv_bfloat16* sQh = sm;
    __nv_bfloat16* sQl = sQh + 64*AP;
    __nv_bfloat16* sKh = sQl + 64*AP;
    __nv_bfloat16* sKl = sKh + 64*AP;
    __nv_bfloat16* sVh = sKl + 64*AP;
    __nv_bfloat16* sVl = sVh + 128*VP;

    const int tid  = threadIdx.x;
    const int lane = tid & 31;
    const int wid  = tid >> 5;
    const int g    = lane >> 2;
    const int t    = lane & 3;

    const int qt = gridDim.x - 1 - blockIdx.x;   // LPT ordering
    const int h  = blockIdx.y;
    const int b  = blockIdx.z;
    const int q0 = qt * 64;

    const long qbase = ((long)(b*SEQ + q0))*DMODEL + h*HDIM;
#pragma unroll
    for (int i = 0; i < 8; i++) {
        int u = tid + 128*i;
        int r = u >> 4, c = (u & 15)*8;
        *(uint4*)(sQh + r*AP + c) = *(const uint4*)(Qh + qbase + (long)r*DMODEL + c);
        *(uint4*)(sQl + r*AP + c) = *(const uint4*)(Ql + qbase + (long)r*DMODEL + c);
    }

    float accO[16][4];
#pragma unroll
    for (int nb = 0; nb < 16; nb++)
#pragma unroll
        for (int c = 0; c < 4; c++) accO[nb][c] = 0.f;
    float m2[2] = {-1e30f, -1e30f};
    float lsum[2] = {0.f, 0.f};

    const float SC2 = 0.08838834764831845f * 1.4426950408889634f;
    const long vtbase = ((long)((b*NHEAD + h)*HDIM))*SEQ;

    for (int kt = 0; kt <= qt; kt++) {
        const int k0 = kt * 64;
        const long kbase = ((long)(b*SEQ + k0))*DMODEL + h*HDIM;
#pragma unroll
        for (int i = 0; i < 8; i++) {
            int u = tid + 128*i;
            int r = u >> 4, c = (u & 15)*8;
            *(uint4*)(sKh + r*AP + c) = *(const uint4*)(Kh + kbase + (long)r*DMODEL + c);
            *(uint4*)(sKl + r*AP + c) = *(const uint4*)(Kl + kbase + (long)r*DMODEL + c);
        }
#pragma unroll
        for (int i = 0; i < 8; i++) {
            int u = tid + 128*i;
            int d = u >> 3, c = (u & 7)*8;
            *(uint4*)(sVh + d*VP + c) = *(const uint4*)(Vth + vtbase + (long)d*SEQ + k0 + c);
            *(uint4*)(sVl + d*VP + c) = *(const uint4*)(Vtl + vtbase + (long)d*SEQ + k0 + c);
        }
        __syncthreads();

        float s[8][4];
#pragma unroll
        for (int nb = 0; nb < 8; nb++)
#pragma unroll
            for (int c = 0; c < 4; c++) s[nb][c] = 0.f;

        const uint32_t* Qh32 = (const uint32_t*)sQh;
        const uint32_t* Ql32 = (const uint32_t*)sQl;
        const uint32_t* Kh32 = (const uint32_t*)sKh;
        const uint32_t* Kl32 = (const uint32_t*)sKl;
        const int rq = wid*16 + g;
#pragma unroll
        for (int kc = 0; kc < 8; kc++) {
            int w0 = rq*(AP/2) + kc*8 + t;
            int w1 = w0 + 8*(AP/2);
            uint32_t ah[4] = {Qh32[w0], Qh32[w1], Qh32[w0+4], Qh32[w1+4]};
            uint32_t al[4] = {Ql32[w0], Ql32[w1], Ql32[w0+4], Ql32[w1+4]};
#pragma unroll
            for (int nb = 0; nb < 8; nb++) {
                int wb = (nb*8 + g)*(AP/2) + kc*8 + t;
                uint32_t bh[2] = {Kh32[wb], Kh32[wb+4]};
                uint32_t bl[2] = {Kl32[wb], Kl32[wb+4]};
                mma_bf16(s[nb], ah, bh);
                mma_bf16(s[nb], ah, bl);
                mma_bf16(s[nb], al, bh);
            }
        }

        if (kt == qt) {
            const int r0 = wid*16 + g, r1 = r0 + 8;
#pragma unroll
            for (int nb = 0; nb < 8; nb++) {
                int c0 = nb*8 + 2*t, c1 = c0 + 1;
                if (c0 > r0) s[nb][0] = -1e30f;
                if (c1 > r0) s[nb][1] = -1e30f;
                if (c0 > r1) s[nb][2] = -1e30f;
                if (c1 > r1) s[nb][3] = -1e30f;
            }
        }

        float mx0 = -1e30f, mx1 = -1e30f;
#pragma unroll
        for (int nb = 0; nb < 8; nb++) {
            mx0 = fmaxf(mx0, fmaxf(s[nb][0], s[nb][1]));
            mx1 = fmaxf(mx1, fmaxf(s[nb][2], s[nb][3]));
        }
        mx0 *= SC2; mx1 *= SC2;
#pragma unroll
        for (int off = 1; off <= 2; off <<= 1) {
            mx0 = fmaxf(mx0, __shfl_xor_sync(0xffffffffu, mx0, off));
            mx1 = fmaxf(mx1, __shfl_xor_sync(0xffffffffu, mx1, off));
        }
        float mn0 = fmaxf(m2[0], mx0), mn1 = fmaxf(m2[1], mx1);
        float corr0 = exp2f(m2[0] - mn0), corr1 = exp2f(m2[1] - mn1);
        float sum0 = 0.f, sum1 = 0.f;
#pragma unroll
        for (int nb = 0; nb < 8; nb++) {
            s[nb][0] = exp2f(s[nb][0]*SC2 - mn0);
            s[nb][1] = exp2f(s[nb][1]*SC2 - mn0);
            s[nb][2] = exp2f(s[nb][2]*SC2 - mn1);
            s[nb][3] = exp2f(s[nb][3]*SC2 - mn1);
            sum0 += s[nb][0] + s[nb][1];
            sum1 += s[nb][2] + s[nb][3];
        }
#pragma unroll
        for (int off = 1; off <= 2; off <<= 1) {
            sum0 += __shfl_xor_sync(0xffffffffu, sum0, off);
            sum1 += __shfl_xor_sync(0xffffffffu, sum1, off);
        }
        lsum[0] = lsum[0]*corr0 + sum0;
        lsum[1] = lsum[1]*corr1 + sum1;
        m2[0] = mn0; m2[1] = mn1;
#pragma unroll
        for (int nb = 0; nb < 16; nb++) {
            accO[nb][0] *= corr0; accO[nb][1] *= corr0;
            accO[nb][2] *= corr1; accO[nb][3] *= corr1;
        }

        uint32_t pah[4][4], pal[4][4];
#pragma unroll
        for (int kc = 0; kc < 4; kc++) {
            pah[kc][0] = pack_split(s[2*kc][0],   s[2*kc][1],   pal[kc][0]);
            pah[kc][1] = pack_split(s[2*kc][2],   s[2*kc][3],   pal[kc][1]);
            pah[kc][2] = pack_split(s[2*kc+1][0], s[2*kc+1][1], pal[kc][2]);
            pah[kc][3] = pack_split(s[2*kc+1][2], s[2*kc+1][3], pal[kc][3]);
        }

        const uint32_t* Vh32 = (const uint32_t*)sVh;
        const uint32_t* Vl32 = (const uint32_t*)sVl;
#pragma unroll
        for (int kc = 0; kc < 4; kc++) {
#pragma unroll
            for (int nb = 0; nb < 16; nb++) {
                int wb = (nb*8 + g)*(VP/2) + kc*8 + t;
                uint32_t bh[2] = {Vh32[wb], Vh32[wb+4]};
                uint32_t bl[2] = {Vl32[wb], Vl32[wb+4]};
                mma_bf16(accO[nb], pah[kc], bh);
                mma_bf16(accO[nb], pah[kc], bl);
                mma_bf16(accO[nb], pal[kc], bh);
            }
        }
        __syncthreads();
    }

    const float inv0 = 1.f / lsum[0], inv1 = 1.f / lsum[1];
    const long obase = ((long)(b*SEQ + q0 + wid*16))*DMODEL + h*HDIM;
#pragma unroll
    for (int nb = 0; nb < 16; nb++) {
        int col = nb*8 + 2*t;
        uint32_t l0, l1;
        uint32_t h0 = pack_split(accO[nb][0]*inv0, accO[nb][1]*inv0, l0);
        uint32_t h1 = pack_split(accO[nb][2]*inv1, accO[nb][3]*inv1, l1);
        *(uint32_t*)(Ch + obase + (long)g*DMODEL + col)     = h0;
        *(uint32_t*)(Cl + obase + (long)g*DMODEL + col)     = l0;
        *(uint32_t*)(Ch + obase + (long)(g+8)*DMODEL + col) = h1;
        *(uint32_t*)(Cl + obase + (long)(g+8)*DMODEL + col) = l1;
    }
}

// ---------------------------------------------------------------------------
// Host launcher
// ---------------------------------------------------------------------------
extern "C" void kernel_launch(void* const* d_in, const int* in_sizes, int n_in,
                              void* d_out, int out_size)
{
    const float* x  = (const float*)d_in[0];
    const float* wq = (const float*)d_in[1];
    const float* wk = (const float*)d_in[2];
    const float* wv = (const float*)d_in[3];
    const float* wo = (const float*)d_in[4];
    const float* bo = (const float*)d_in[5];
    float* out = (float*)d_out;

    __nv_bfloat16 *xs_h, *xs_l, *wqh, *wql, *wkh, *wkl, *wvh, *wvl, *woh, *wol;
    __nv_bfloat16 *qh, *ql, *kh, *kl, *vh, *vl, *vth, *vtl, *ch, *cl;
    cudaGetSymbolAddress((void**)&xs_h, g_xs_h); cudaGetSymbolAddress((void**)&xs_l, g_xs_l);
    cudaGetSymbolAddress((void**)&wqh, g_wq_h);  cudaGetSymbolAddress((void**)&wql, g_wq_l);
    cudaGetSymbolAddress((void**)&wkh, g_wk_h);  cudaGetSymbolAddress((void**)&wkl, g_wk_l);
    cudaGetSymbolAddress((void**)&wvh, g_wv_h);  cudaGetSymbolAddress((void**)&wvl, g_wv_l);
    cudaGetSymbolAddress((void**)&woh, g_wo_h);  cudaGetSymbolAddress((void**)&wol, g_wo_l);
    cudaGetSymbolAddress((void**)&qh, g_q_h);    cudaGetSymbolAddress((void**)&ql, g_q_l);
    cudaGetSymbolAddress((void**)&kh, g_k_h);    cudaGetSymbolAddress((void**)&kl, g_k_l);
    cudaGetSymbolAddress((void**)&vh, g_v_h);    cudaGetSymbolAddress((void**)&vl, g_v_l);
    cudaGetSymbolAddress((void**)&vth, g_vt_h);  cudaGetSymbolAddress((void**)&vtl, g_vt_l);
    cudaGetSymbolAddress((void**)&ch, g_c_h);    cudaGetSymbolAddress((void**)&cl, g_c_l);

    static bool configured = false;
    if (!configured) {
        cudaFuncSetAttribute(gemm2<true>,  cudaFuncAttributeMaxDynamicSharedMemorySize, GEMM_SMEM);
        cudaFuncSetAttribute(gemm2<false>, cudaFuncAttributeMaxDynamicSharedMemorySize, GEMM_SMEM);
        cudaFuncSetAttribute(attn_mma, cudaFuncAttributeMaxDynamicSharedMemorySize, ATTN_SMEM);
        configured = true;
    }

    // 1) split inputs
    split_kernel<<<(NTOK/4 + 255)/256, 256>>>((const float4*)x,  (uint2*)xs_h, (uint2*)xs_l, NTOK/4);
    split_kernel<<<(NW/4 + 255)/256, 256>>>((const float4*)wq, (uint2*)wqh, (uint2*)wql, NW/4);
    split_kernel<<<(NW/4 + 255)/256, 256>>>((const float4*)wk, (uint2*)wkh, (uint2*)wkl, NW/4);
    split_kernel<<<(NW/4 + 255)/256, 256>>>((const float4*)wv, (uint2*)wvh, (uint2*)wvl, NW/4);
    split_kernel<<<(NW/4 + 255)/256, 256>>>((const float4*)wo, (uint2*)woh, (uint2*)wol, NW/4);

    // 2) fused QKV projection: one launch, grid (48, 64)
    {
        GemmArgs a = {};
        a.Ah = xs_h; a.Al = xs_l;
        a.Bh0 = wqh; a.Bl0 = wql; a.Bh1 = wkh; a.Bl1 = wkl; a.Bh2 = wvh; a.Bl2 = wvl;
        a.Ch0 = qh;  a.Cl0 = ql;  a.Ch1 = kh;  a.Cl1 = kl;  a.Ch2 = vh;  a.Cl2 = vl;
        gemm2<true><<<dim3(48, MTOT/64), 128, GEMM_SMEM>>>(a);
    }

    // 3) V transpose (per batch 2048x2048), hi and lo fused (z: b + 2*sel)
    transpose_bf16<<<dim3(64, 64, 2*BATCH), 256>>>(vh, vth, vl, vtl);

    // 4) attention
    attn_mma<<<dim3(SEQ/64, NHEAD, BATCH), 128, ATTN_SMEM>>>(qh, ql, kh, kl, vth, vtl, ch, cl);

    // 5) output projection (fp32 + bias)
    {
        GemmArgs a = {};
        a.Ah = ch; a.Al = cl;
        a.Bh0 = woh; a.Bl0 = wol; a.Bh1 = woh; a.Bl1 = wol; a.Bh2 = woh; a.Bl2 = wol;
        a.Cf = out; a.bias = bo;
        gemm2<false><<<dim3(16, MTOT/64), 128, GEMM_SMEM>>>(a);
    }
}

// round 11
// speedup vs baseline: 1.3830x; 1.0573x over previous
#include <cuda_runtime.h>
#include <cuda_bf16.h>
#include <cstdint>

#define BATCH 2
#define SEQ 2048
#define DMODEL 2048
#define NHEAD 16
#define HDIM 128
#define MTOT (BATCH*SEQ)          // 4096
#define NTOK (MTOT*DMODEL)        // 8388608
#define NW   (DMODEL*DMODEL)      // 4194304

// ---------------- scratch (device globals: allocation-free) ----------------
__device__ alignas(16) __nv_bfloat16 g_xs_h[NTOK], g_xs_l[NTOK];
__device__ alignas(16) __nv_bfloat16 g_wq_h[NW],  g_wq_l[NW];
__device__ alignas(16) __nv_bfloat16 g_wk_h[NW],  g_wk_l[NW];
__device__ alignas(16) __nv_bfloat16 g_wv_h[NW],  g_wv_l[NW];
__device__ alignas(16) __nv_bfloat16 g_wo_h[NW],  g_wo_l[NW];
__device__ alignas(16) __nv_bfloat16 g_q_h[NTOK], g_q_l[NTOK];
__device__ alignas(16) __nv_bfloat16 g_k_h[NTOK], g_k_l[NTOK];
__device__ alignas(16) __nv_bfloat16 g_v_h[NTOK], g_v_l[NTOK];
__device__ alignas(16) __nv_bfloat16 g_vt_h[NTOK], g_vt_l[NTOK];
__device__ alignas(16) __nv_bfloat16 g_c_h[NTOK], g_c_l[NTOK];

// ---------------- helpers ----------------
__device__ __forceinline__ uint32_t smem_u32(const void* p) {
    uint32_t a;
    asm("{ .reg .u64 t; cvta.to.shared.u64 t, %1; cvt.u32.u64 %0, t; }" : "=r"(a) : "l"(p));
    return a;
}

__device__ __forceinline__ void mma_bf16(float* c, const uint32_t* a, const uint32_t* b)
{
    asm volatile(
        "mma.sync.aligned.m16n8k16.row.col.f32.bf16.bf16.f32 "
        "{%0,%1,%2,%3}, {%4,%5,%6,%7}, {%8,%9}, {%0,%1,%2,%3};\n"
        : "+f"(c[0]), "+f"(c[1]), "+f"(c[2]), "+f"(c[3])
        : "r"(a[0]), "r"(a[1]), "r"(a[2]), "r"(a[3]), "r"(b[0]), "r"(b[1]));
}

__device__ __forceinline__ void ldsm4(uint32_t& r0, uint32_t& r1, uint32_t& r2, uint32_t& r3,
                                      uint32_t addr)
{
    asm volatile("ldmatrix.sync.aligned.m8n8.x4.shared.b16 {%0,%1,%2,%3}, [%4];"
                 : "=r"(r0), "=r"(r1), "=r"(r2), "=r"(r3) : "r"(addr));
}

__device__ __forceinline__ uint32_t pack_split(float x, float y, uint32_t& lo_out)
{
    __nv_bfloat16 hx = __float2bfloat16(x);
    __nv_bfloat16 hy = __float2bfloat16(y);
    __nv_bfloat16 lx = __float2bfloat16(x - __bfloat162float(hx));
    __nv_bfloat16 ly = __float2bfloat16(y - __bfloat162float(hy));
    __nv_bfloat162 h2 = __halves2bfloat162(hx, hy);
    __nv_bfloat162 l2 = __halves2bfloat162(lx, ly);
    lo_out = *(uint32_t*)&l2;
    return *(uint32_t*)&h2;
}

// cp.async primitives
__device__ __forceinline__ void cp16(uint32_t dst, const void* src) {
    asm volatile("cp.async.cg.shared.global [%0], [%1], 16;" :: "r"(dst), "l"(src));
}
__device__ __forceinline__ void cp_commit() {
    asm volatile("cp.async.commit_group;" ::: "memory");
}
template<int N> __device__ __forceinline__ void cp_wait() {
    asm volatile("cp.async.wait_group %0;" :: "n"(N) : "memory");
}

// ---------------- fp32 -> bf16 hi/lo split ----------------
__global__ void split_kernel(const float4* __restrict__ src,
                             uint2* __restrict__ hi, uint2* __restrict__ lo, int n4)
{
    int i = blockIdx.x * blockDim.x + threadIdx.x;
    if (i >= n4) return;
    float4 v = src[i];
    uint32_t l0, l1;
    uint32_t h0 = pack_split(v.x, v.y, l0);
    uint32_t h1 = pack_split(v.z, v.w, l1);
    hi[i] = make_uint2(h0, h1);
    lo[i] = make_uint2(l0, l1);
}

// ---------------- per-batch 2048x2048 bf16 transpose (hi+lo fused) ----------
__global__ void transpose_bf16(const __nv_bfloat16* __restrict__ in_h,
                               __nv_bfloat16* __restrict__ out_h,
                               const __nv_bfloat16* __restrict__ in_l,
                               __nv_bfloat16* __restrict__ out_l)
{
    __shared__ __nv_bfloat16 tile[32][33];
    const int bx = blockIdx.x * 32;
    const int by = blockIdx.y * 32;
    const int b  = blockIdx.z & 1;
    const int sel = blockIdx.z >> 1;
    const __nv_bfloat16* in  = sel ? in_l  : in_h;
    __nv_bfloat16*       out = sel ? out_l : out_h;
    const long boff = (long)b * 2048 * 2048;
    const int tx = threadIdx.x & 31;
    const int ty = threadIdx.x >> 5;
#pragma unroll
    for (int j = 0; j < 4; j++) {
        int sl = ty + j*8;
        tile[sl][tx] = in[boff + (long)(by + sl)*2048 + bx + tx];
    }
    __syncthreads();
#pragma unroll
    for (int j = 0; j < 4; j++) {
        int hl = ty + j*8;
        out[boff + (long)(bx + hl)*2048 + by + tx] = tile[tx][hl];
    }
}

// ---------------------------------------------------------------------------
// bf16x3 GEMM, BM=64 x BN=128, 128 threads, 2-stage cp.async, 3 CTAs/SM.
// Fragment loads via ldmatrix.x4 (conflict-free at 80B pitch).
// ---------------------------------------------------------------------------
#define G2BK 32
#define S_AH 0
#define S_AL 5120
#define S_BH 10240
#define S_BL 20480
#define STAGE2 30720
#define NST 2
#define GEMM_SMEM (NST*STAGE2)     // 61440 -> 3 CTAs/SM

struct GemmArgs {
    const __nv_bfloat16 *Ah, *Al;
    const __nv_bfloat16 *Bh0, *Bl0, *Bh1, *Bl1, *Bh2, *Bl2;
    float* Cf;
    __nv_bfloat16 *Ch0, *Cl0, *Ch1, *Cl1, *Ch2, *Cl2;
    const float* bias;
};

__device__ __forceinline__ void issue_tile2(uint32_t sb,
    const __nv_bfloat16* __restrict__ Ah, const __nv_bfloat16* __restrict__ Al,
    const __nv_bfloat16* __restrict__ Bh, const __nv_bfloat16* __restrict__ Bl,
    int m0, int n0, int kofs, int tid)
{
#pragma unroll
    for (int i = 0; i < 2; i++) {
        int idx = tid + 128*i;
        int r = idx >> 2, c = idx & 3;
        uint32_t so = r*80 + c*16;
        long ga = (long)(m0 + r)*DMODEL + kofs + c*8;
        cp16(sb + S_AH + so, Ah + ga);
        cp16(sb + S_AL + so, Al + ga);
    }
#pragma unroll
    for (int i = 0; i < 4; i++) {
        int idx = tid + 128*i;
        int r = idx >> 2, c = idx & 3;
        uint32_t so = r*80 + c*16;
        long gb = (long)(n0 + r)*DMODEL + kofs + c*8;
        cp16(sb + S_BH + so, Bh + gb);
        cp16(sb + S_BL + so, Bl + gb);
    }
}

template<bool SPLIT_OUT>
__global__ __launch_bounds__(128, 3)
void gemm2(GemmArgs a)
{
    extern __shared__ __align__(16) char gsm[];
    const uint32_t smb = smem_u32(gsm);

    const int tid  = threadIdx.x;
    const int lane = tid & 31;
    const int wid  = tid >> 5;       // 0..3 (n-split)
    const int g    = lane >> 2;
    const int t    = lane & 3;
    const int sub  = lane & 7;
    const int sel  = lane >> 3;

    // ldmatrix per-lane offsets (pitch 80B)
    const uint32_t aoff = ((sel & 1)*8 + sub)*80u + (uint32_t)(sel >> 1)*16u;
    const uint32_t boff = ((sel >> 1)*8 + sub)*80u + (uint32_t)(sel & 1)*16u;

    const int bsel = blockIdx.x >> 4;
    const int n0   = (blockIdx.x & 15) * 128;
    const int m0   = blockIdx.y * 64;

    const __nv_bfloat16* Bh = (bsel == 0) ? a.Bh0 : (bsel == 1) ? a.Bh1 : a.Bh2;
    const __nv_bfloat16* Bl = (bsel == 0) ? a.Bl0 : (bsel == 1) ? a.Bl1 : a.Bl2;

    float acc[4][4][4];
#pragma unroll
    for (int mf = 0; mf < 4; mf++)
#pragma unroll
        for (int nf = 0; nf < 4; nf++)
#pragma unroll
            for (int c = 0; c < 4; c++) acc[mf][nf][c] = 0.f;

    const int nk = DMODEL / G2BK;   // 64

    issue_tile2(smb,          a.Ah, a.Al, Bh, Bl, m0, n0, 0,    tid);
    cp_commit();
    issue_tile2(smb + STAGE2, a.Ah, a.Al, Bh, Bl, m0, n0, G2BK, tid);
    cp_commit();

    for (int kt = 0; kt < nk; kt++) {
        cp_wait<1>();
        __syncthreads();

        const uint32_t sb32 = smb + (kt & 1)*STAGE2;
        const uint32_t sbAH = sb32 + S_AH;
        const uint32_t sbAL = sb32 + S_AL;
        const uint32_t sbBH = sb32 + S_BH + (uint32_t)(wid*32)*80u;
        const uint32_t sbBL = sb32 + S_BL + (uint32_t)(wid*32)*80u;

#pragma unroll
        for (int ks = 0; ks < 2; ks++) {
            const uint32_t kb = ks*32;
            uint32_t ah[4][4], al[4][4], bh[4][2], bl[4][2];
#pragma unroll
            for (int mf = 0; mf < 4; mf++) {
                ldsm4(ah[mf][0], ah[mf][1], ah[mf][2], ah[mf][3],
                      sbAH + (uint32_t)(mf*16)*80u + kb + aoff);
                ldsm4(al[mf][0], al[mf][1], al[mf][2], al[mf][3],
                      sbAL + (uint32_t)(mf*16)*80u + kb + aoff);
            }
#pragma unroll
            for (int p = 0; p < 2; p++) {
                ldsm4(bh[2*p][0], bh[2*p][1], bh[2*p+1][0], bh[2*p+1][1],
                      sbBH + (uint32_t)(p*16)*80u + kb + boff);
                ldsm4(bl[2*p][0], bl[2*p][1], bl[2*p+1][0], bl[2*p+1][1],
                      sbBL + (uint32_t)(p*16)*80u + kb + boff);
            }
#pragma unroll
            for (int mf = 0; mf < 4; mf++)
#pragma unroll
                for (int nf = 0; nf < 4; nf++)
                    mma_bf16(acc[mf][nf], ah[mf], bh[nf]);
#pragma unroll
            for (int mf = 0; mf < 4; mf++)
#pragma unroll
                for (int nf = 0; nf < 4; nf++)
                    mma_bf16(acc[mf][nf], ah[mf], bl[nf]);
#pragma unroll
            for (int mf = 0; mf < 4; mf++)
#pragma unroll
                for (int nf = 0; nf < 4; nf++)
                    mma_bf16(acc[mf][nf], al[mf], bh[nf]);
        }
        __syncthreads();

        if (kt + 2 < nk)
            issue_tile2(smb + (kt & 1)*STAGE2,
                        a.Ah, a.Al, Bh, Bl, m0, n0, (kt+2)*G2BK, tid);
        cp_commit();
    }

    __nv_bfloat16* Ch = (bsel == 0) ? a.Ch0 : (bsel == 1) ? a.Ch1 : a.Ch2;
    __nv_bfloat16* Cl = (bsel == 0) ? a.Cl0 : (bsel == 1) ? a.Cl1 : a.Cl2;

#pragma unroll
    for (int nf = 0; nf < 4; nf++) {
        int col = n0 + wid*32 + nf*8 + 2*t;
        float b0 = 0.f, b1 = 0.f;
        if (!SPLIT_OUT && a.bias) { b0 = a.bias[col]; b1 = a.bias[col + 1]; }
#pragma unroll
        for (int mf = 0; mf < 4; mf++) {
            int row = m0 + mf*16 + g;
            if (SPLIT_OUT) {
                uint32_t l0, l1;
                uint32_t h0 = pack_split(acc[mf][nf][0], acc[mf][nf][1], l0);
                uint32_t h1 = pack_split(acc[mf][nf][2], acc[mf][nf][3], l1);
                *(uint32_t*)(Ch + (long)row*DMODEL + col)     = h0;
                *(uint32_t*)(Cl + (long)row*DMODEL + col)     = l0;
                *(uint32_t*)(Ch + (long)(row+8)*DMODEL + col) = h1;
                *(uint32_t*)(Cl + (long)(row+8)*DMODEL + col) = l1;
            } else {
                *(float2*)(a.Cf + (long)row*DMODEL + col)     = make_float2(acc[mf][nf][0]+b0, acc[mf][nf][1]+b1);
                *(float2*)(a.Cf + (long)(row+8)*DMODEL + col) = make_float2(acc[mf][nf][2]+b0, acc[mf][nf][3]+b1);
            }
        }
    }
}

// ---------------------------------------------------------------------------
// Tensor-core causal flash attention, bf16x3, ldmatrix fragment loads.
// ---------------------------------------------------------------------------
#define AP 136
#define VP 72
#define ATTN_SMEM ((4*64*AP + 2*128*VP)*2)   // 106496 bytes

__global__ __launch_bounds__(128)
void attn_mma(const __nv_bfloat16* __restrict__ Qh, const __nv_bfloat16* __restrict__ Ql,
              const __nv_bfloat16* __restrict__ Kh, const __nv_bfloat16* __restrict__ Kl,
              const __nv_bfloat16* __restrict__ Vth, const __nv_bfloat16* __restrict__ Vtl,
              __nv_bfloat16* __restrict__ Ch, __nv_bfloat16* __restrict__ Cl)
{
    extern __shared__ __nv_bfloat16 sm[];
    __nv_bfloat16* sQh = sm;
    __nv_bfloat16* sQl = sQh + 64*AP;
    __nv_bfloat16* sKh = sQl + 64*AP;
    __nv_bfloat16* sKl = sKh + 64*AP;
    __nv_bfloat16* sVh = sKl + 64*AP;
    __nv_bfloat16* sVl = sVh + 128*VP;

    const uint32_t smb   = smem_u32(sm);
    const uint32_t sQh32 = smb;
    const uint32_t sQl32 = smb + 1*64*AP*2;
    const uint32_t sKh32 = smb + 2*64*AP*2;
    const uint32_t sKl32 = smb + 3*64*AP*2;
    const uint32_t sVh32 = smb + 4*64*AP*2;
    const uint32_t sVl32 = sVh32 + 128*VP*2;

    const int tid  = threadIdx.x;
    const int lane = tid & 31;
    const int wid  = tid >> 5;
    const int g    = lane >> 2;
    const int t    = lane & 3;
    const int sub  = lane & 7;
    const int sel  = lane >> 3;

    const uint32_t qoff = ((sel & 1)*8 + sub)*(AP*2u) + (uint32_t)(sel >> 1)*16u;
    const uint32_t koff = ((sel >> 1)*8 + sub)*(AP*2u) + (uint32_t)(sel & 1)*16u;
    const uint32_t voff = ((sel >> 1)*8 + sub)*(VP*2u) + (uint32_t)(sel & 1)*16u;

    const int qt = gridDim.x - 1 - blockIdx.x;   // LPT ordering
    const int h  = blockIdx.y;
    const int b  = blockIdx.z;
    const int q0 = qt * 64;

    const long qbase = ((long)(b*SEQ + q0))*DMODEL + h*HDIM;
#pragma unroll
    for (int i = 0; i < 8; i++) {
        int u = tid + 128*i;
        int r = u >> 4, c = (u & 15)*8;
        *(uint4*)(sQh + r*AP + c) = *(const uint4*)(Qh + qbase + (long)r*DMODEL + c);
        *(uint4*)(sQl + r*AP + c) = *(const uint4*)(Ql + qbase + (long)r*DMODEL + c);
    }

    float accO[16][4];
#pragma unroll
    for (int nb = 0; nb < 16; nb++)
#pragma unroll
        for (int c = 0; c < 4; c++) accO[nb][c] = 0.f;
    float m2[2] = {-1e30f, -1e30f};
    float lsum[2] = {0.f, 0.f};

    const float SC2 = 0.08838834764831845f * 1.4426950408889634f;
    const long vtbase = ((long)((b*NHEAD + h)*HDIM))*SEQ;

    for (int kt = 0; kt <= qt; kt++) {
        const int k0 = kt * 64;
        const long kbase = ((long)(b*SEQ + k0))*DMODEL + h*HDIM;
#pragma unroll
        for (int i = 0; i < 8; i++) {
            int u = tid + 128*i;
            int r = u >> 4, c = (u & 15)*8;
            *(uint4*)(sKh + r*AP + c) = *(const uint4*)(Kh + kbase + (long)r*DMODEL + c);
            *(uint4*)(sKl + r*AP + c) = *(const uint4*)(Kl + kbase + (long)r*DMODEL + c);
        }
#pragma unroll
        for (int i = 0; i < 8; i++) {
            int u = tid + 128*i;
            int d = u >> 3, c = (u & 7)*8;
            *(uint4*)(sVh + d*VP + c) = *(const uint4*)(Vth + vtbase + (long)d*SEQ + k0 + c);
            *(uint4*)(sVl + d*VP + c) = *(const uint4*)(Vtl + vtbase + (long)d*SEQ + k0 + c);
        }
        __syncthreads();

        // ---- S = Q @ K^T (bf16x3, ldmatrix) ----
        float s[8][4];
#pragma unroll
        for (int nb = 0; nb < 8; nb++)
#pragma unroll
            for (int c = 0; c < 4; c++) s[nb][c] = 0.f;

        const uint32_t qbaseb = (uint32_t)(wid*16)*(AP*2u);
#pragma unroll
        for (int kc = 0; kc < 8; kc++) {
            const uint32_t kb = kc*32;
            uint32_t ah[4], al[4];
            ldsm4(ah[0], ah[1], ah[2], ah[3], sQh32 + qbaseb + kb + qoff);
            ldsm4(al[0], al[1], al[2], al[3], sQl32 + qbaseb + kb + qoff);
#pragma unroll
            for (int p = 0; p < 4; p++) {
                uint32_t bh[2][2], bl[2][2];
                ldsm4(bh[0][0], bh[0][1], bh[1][0], bh[1][1],
                      sKh32 + (uint32_t)(p*16)*(AP*2u) + kb + koff);
                ldsm4(bl[0][0], bl[0][1], bl[1][0], bl[1][1],
                      sKl32 + (uint32_t)(p*16)*(AP*2u) + kb + koff);
#pragma unroll
                for (int e = 0; e < 2; e++) {
                    mma_bf16(s[2*p + e], ah, bh[e]);
                    mma_bf16(s[2*p + e], ah, bl[e]);
                    mma_bf16(s[2*p + e], al, bh[e]);
                }
            }
        }

        if (kt == qt) {
            const int r0 = wid*16 + g, r1 = r0 + 8;
#pragma unroll
            for (int nb = 0; nb < 8; nb++) {
                int c0 = nb*8 + 2*t, c1 = c0 + 1;
                if (c0 > r0) s[nb][0] = -1e30f;
                if (c1 > r0) s[nb][1] = -1e30f;
                if (c0 > r1) s[nb][2] = -1e30f;
                if (c1 > r1) s[nb][3] = -1e30f;
            }
        }

        float mx0 = -1e30f, mx1 = -1e30f;
#pragma unroll
        for (int nb = 0; nb < 8; nb++) {
            mx0 = fmaxf(mx0, fmaxf(s[nb][0], s[nb][1]));
            mx1 = fmaxf(mx1, fmaxf(s[nb][2], s[nb][3]));
        }
        mx0 *= SC2; mx1 *= SC2;
#pragma unroll
        for (int off = 1; off <= 2; off <<= 1) {
            mx0 = fmaxf(mx0, __shfl_xor_sync(0xffffffffu, mx0, off));
            mx1 = fmaxf(mx1, __shfl_xor_sync(0xffffffffu, mx1, off));
        }
        float mn0 = fmaxf(m2[0], mx0), mn1 = fmaxf(m2[1], mx1);
        float corr0 = exp2f(m2[0] - mn0), corr1 = exp2f(m2[1] - mn1);
        float sum0 = 0.f, sum1 = 0.f;
#pragma unroll
        for (int nb = 0; nb < 8; nb++) {
            s[nb][0] = exp2f(s[nb][0]*SC2 - mn0);
            s[nb][1] = exp2f(s[nb][1]*SC2 - mn0);
            s[nb][2] = exp2f(s[nb][2]*SC2 - mn1);
            s[nb][3] = exp2f(s[nb][3]*SC2 - mn1);
            sum0 += s[nb][0] + s[nb][1];
            sum1 += s[nb][2] + s[nb][3];
        }
#pragma unroll
        for (int off = 1; off <= 2; off <<= 1) {
            sum0 += __shfl_xor_sync(0xffffffffu, sum0, off);
            sum1 += __shfl_xor_sync(0xffffffffu, sum1, off);
        }
        lsum[0] = lsum[0]*corr0 + sum0;
        lsum[1] = lsum[1]*corr1 + sum1;
        m2[0] = mn0; m2[1] = mn1;
#pragma unroll
        for (int nb = 0; nb < 16; nb++) {
            accO[nb][0] *= corr0; accO[nb][1] *= corr0;
            accO[nb][2] *= corr1; accO[nb][3] *= corr1;
        }

        uint32_t pah[4][4], pal[4][4];
#pragma unroll
        for (int kc = 0; kc < 4; kc++) {
            pah[kc][0] = pack_split(s[2*kc][0],   s[2*kc][1],   pal[kc][0]);
            pah[kc][1] = pack_split(s[2*kc][2],   s[2*kc][3],   pal[kc][1]);
            pah[kc][2] = pack_split(s[2*kc+1][0], s[2*kc+1][1], pal[kc][2]);
            pah[kc][3] = pack_split(s[2*kc+1][2], s[2*kc+1][3], pal[kc][3]);
        }

        // ---- O += P @ V (bf16x3, ldmatrix) ----
#pragma unroll
        for (int kc = 0; kc < 4; kc++) {
            const uint32_t kb = kc*32;
#pragma unroll
            for (int p = 0; p < 8; p++) {
                uint32_t vh[2][2], vl[2][2];
                ldsm4(vh[0][0], vh[0][1], vh[1][0], vh[1][1],
                      sVh32 + (uint32_t)(p*16)*(VP*2u) + kb + voff);
                ldsm4(vl[0][0], vl[0][1], vl[1][0], vl[1][1],
                      sVl32 + (uint32_t)(p*16)*(VP*2u) + kb + voff);
#pragma unroll
                for (int e = 0; e < 2; e++) {
                    mma_bf16(accO[2*p + e], pah[kc], vh[e]);
                    mma_bf16(accO[2*p + e], pah[kc], vl[e]);
                    mma_bf16(accO[2*p + e], pal[kc], vh[e]);
                }
            }
        }
        __syncthreads();
    }

    const float inv0 = 1.f / lsum[0], inv1 = 1.f / lsum[1];
    const long obase = ((long)(b*SEQ + q0 + wid*16))*DMODEL + h*HDIM;
#pragma unroll
    for (int nb = 0; nb < 16; nb++) {
        int col = nb*8 + 2*t;
        uint32_t l0, l1;
        uint32_t h0 = pack_split(accO[nb][0]*inv0, accO[nb][1]*inv0, l0);
        uint32_t h1 = pack_split(accO[nb][2]*inv1, accO[nb][3]*inv1, l1);
        *(uint32_t*)(Ch + obase + (long)g*DMODEL + col)     = h0;
        *(uint32_t*)(Cl + obase + (long)g*DMODEL + col)     = l0;
        *(uint32_t*)(Ch + obase + (long)(g+8)*DMODEL + col) = h1;
        *(uint32_t*)(Cl + obase + (long)(g+8)*DMODEL + col) = l1;
    }
}

// ---------------------------------------------------------------------------
// Host launcher
// ---------------------------------------------------------------------------
extern "C" void kernel_launch(void* const* d_in, const int* in_sizes, int n_in,
                              void* d_out, int out_size)
{
    const float* x  = (const float*)d_in[0];
    const float* wq = (const float*)d_in[1];
    const float* wk = (const float*)d_in[2];
    const float* wv = (const float*)d_in[3];
    const float* wo = (const float*)d_in[4];
    const float* bo = (const float*)d_in[5];
    float* out = (float*)d_out;

    __nv_bfloat16 *xs_h, *xs_l, *wqh, *wql, *wkh, *wkl, *wvh, *wvl, *woh, *wol;
    __nv_bfloat16 *qh, *ql, *kh, *kl, *vh, *vl, *vth, *vtl, *ch, *cl;
    cudaGetSymbolAddress((void**)&xs_h, g_xs_h); cudaGetSymbolAddress((void**)&xs_l, g_xs_l);
    cudaGetSymbolAddress((void**)&wqh, g_wq_h);  cudaGetSymbolAddress((void**)&wql, g_wq_l);
    cudaGetSymbolAddress((void**)&wkh, g_wk_h);  cudaGetSymbolAddress((void**)&wkl, g_wk_l);
    cudaGetSymbolAddress((void**)&wvh, g_wv_h);  cudaGetSymbolAddress((void**)&wvl, g_wv_l);
    cudaGetSymbolAddress((void**)&woh, g_wo_h);  cudaGetSymbolAddress((void**)&wol, g_wo_l);
    cudaGetSymbolAddress((void**)&qh, g_q_h);    cudaGetSymbolAddress((void**)&ql, g_q_l);
    cudaGetSymbolAddress((void**)&kh, g_k_h);    cudaGetSymbolAddress((void**)&kl, g_k_l);
    cudaGetSymbolAddress((void**)&vh, g_v_h);    cudaGetSymbolAddress((void**)&vl, g_v_l);
    cudaGetSymbolAddress((void**)&vth, g_vt_h);  cudaGetSymbolAddress((void**)&vtl, g_vt_l);
    cudaGetSymbolAddress((void**)&ch, g_c_h);    cudaGetSymbolAddress((void**)&cl, g_c_l);

    static bool configured = false;
    if (!configured) {
        cudaFuncSetAttribute(gemm2<true>,  cudaFuncAttributeMaxDynamicSharedMemorySize, GEMM_SMEM);
        cudaFuncSetAttribute(gemm2<false>, cudaFuncAttributeMaxDynamicSharedMemorySize, GEMM_SMEM);
        cudaFuncSetAttribute(attn_mma, cudaFuncAttributeMaxDynamicSharedMemorySize, ATTN_SMEM);
        configured = true;
    }

    // 1) split inputs
    split_kernel<<<(NTOK/4 + 255)/256, 256>>>((const float4*)x,  (uint2*)xs_h, (uint2*)xs_l, NTOK/4);
    split_kernel<<<(NW/4 + 255)/256, 256>>>((const float4*)wq, (uint2*)wqh, (uint2*)wql, NW/4);
    split_kernel<<<(NW/4 + 255)/256, 256>>>((const float4*)wk, (uint2*)wkh, (uint2*)wkl, NW/4);
    split_kernel<<<(NW/4 + 255)/256, 256>>>((const float4*)wv, (uint2*)wvh, (uint2*)wvl, NW/4);
    split_kernel<<<(NW/4 + 255)/256, 256>>>((const float4*)wo, (uint2*)woh, (uint2*)wol, NW/4);

    // 2) fused QKV projection: one launch, grid (48, 64)
    {
        GemmArgs a = {};
        a.Ah = xs_h; a.Al = xs_l;
        a.Bh0 = wqh; a.Bl0 = wql; a.Bh1 = wkh; a.Bl1 = wkl; a.Bh2 = wvh; a.Bl2 = wvl;
        a.Ch0 = qh;  a.Cl0 = ql;  a.Ch1 = kh;  a.Cl1 = kl;  a.Ch2 = vh;  a.Cl2 = vl;
        gemm2<true><<<dim3(48, MTOT/64), 128, GEMM_SMEM>>>(a);
    }

    // 3) V transpose (per batch 2048x2048), hi and lo fused
    transpose_bf16<<<dim3(64, 64, 2*BATCH), 256>>>(vh, vth, vl, vtl);

    // 4) attention
    attn_mma<<<dim3(SEQ/64, NHEAD, BATCH), 128, ATTN_SMEM>>>(qh, ql, kh, kl, vth, vtl, ch, cl);

    // 5) output projection (fp32 + bias)
    {
        GemmArgs a = {};
        a.Ah = ch; a.Al = cl;
        a.Bh0 = woh; a.Bl0 = wol; a.Bh1 = woh; a.Bl1 = wol; a.Bh2 = woh; a.Bl2 = wol;
        a.Cf = out; a.bias = bo;
        gemm2<false><<<dim3(16, MTOT/64), 128, GEMM_SMEM>>>(a);
    }
}

// round 12
// speedup vs baseline: 1.3910x; 1.0058x over previous
#include <cuda_runtime.h>
#include <cuda_bf16.h>
#include <cstdint>

#define BATCH 2
#define SEQ 2048
#define DMODEL 2048
#define NHEAD 16
#define HDIM 128
#define MTOT (BATCH*SEQ)          // 4096
#define NTOK (MTOT*DMODEL)        // 8388608
#define NW   (DMODEL*DMODEL)      // 4194304

// ---------------- scratch (device globals: allocation-free) ----------------
__device__ alignas(16) __nv_bfloat16 g_xs_h[NTOK], g_xs_l[NTOK];
__device__ alignas(16) __nv_bfloat16 g_wq_h[NW],  g_wq_l[NW];
__device__ alignas(16) __nv_bfloat16 g_wk_h[NW],  g_wk_l[NW];
__device__ alignas(16) __nv_bfloat16 g_wv_h[NW],  g_wv_l[NW];
__device__ alignas(16) __nv_bfloat16 g_wo_h[NW],  g_wo_l[NW];
__device__ alignas(16) __nv_bfloat16 g_q_h[NTOK], g_q_l[NTOK];
__device__ alignas(16) __nv_bfloat16 g_k_h[NTOK], g_k_l[NTOK];
__device__ alignas(16) __nv_bfloat16 g_v_h[NTOK], g_v_l[NTOK];
__device__ alignas(16) __nv_bfloat16 g_vt_h[NTOK], g_vt_l[NTOK];
__device__ alignas(16) __nv_bfloat16 g_c_h[NTOK], g_c_l[NTOK];

// ---------------- helpers ----------------
__device__ __forceinline__ uint32_t smem_u32(const void* p) {
    uint32_t a;
    asm("{ .reg .u64 t; cvta.to.shared.u64 t, %1; cvt.u32.u64 %0, t; }" : "=r"(a) : "l"(p));
    return a;
}

__device__ __forceinline__ void mma_bf16(float* c, const uint32_t* a, const uint32_t* b)
{
    asm volatile(
        "mma.sync.aligned.m16n8k16.row.col.f32.bf16.bf16.f32 "
        "{%0,%1,%2,%3}, {%4,%5,%6,%7}, {%8,%9}, {%0,%1,%2,%3};\n"
        : "+f"(c[0]), "+f"(c[1]), "+f"(c[2]), "+f"(c[3])
        : "r"(a[0]), "r"(a[1]), "r"(a[2]), "r"(a[3]), "r"(b[0]), "r"(b[1]));
}

__device__ __forceinline__ void ldsm4(uint32_t& r0, uint32_t& r1, uint32_t& r2, uint32_t& r3,
                                      uint32_t addr)
{
    asm volatile("ldmatrix.sync.aligned.m8n8.x4.shared.b16 {%0,%1,%2,%3}, [%4];"
                 : "=r"(r0), "=r"(r1), "=r"(r2), "=r"(r3) : "r"(addr));
}

__device__ __forceinline__ uint32_t pack_split(float x, float y, uint32_t& lo_out)
{
    __nv_bfloat16 hx = __float2bfloat16(x);
    __nv_bfloat16 hy = __float2bfloat16(y);
    __nv_bfloat16 lx = __float2bfloat16(x - __bfloat162float(hx));
    __nv_bfloat16 ly = __float2bfloat16(y - __bfloat162float(hy));
    __nv_bfloat162 h2 = __halves2bfloat162(hx, hy);
    __nv_bfloat162 l2 = __halves2bfloat162(lx, ly);
    lo_out = *(uint32_t*)&l2;
    return *(uint32_t*)&h2;
}

// cp.async primitives
__device__ __forceinline__ void cp16(uint32_t dst, const void* src) {
    asm volatile("cp.async.cg.shared.global [%0], [%1], 16;" :: "r"(dst), "l"(src));
}
__device__ __forceinline__ void cp_commit() {
    asm volatile("cp.async.commit_group;" ::: "memory");
}
template<int N> __device__ __forceinline__ void cp_wait() {
    asm volatile("cp.async.wait_group %0;" :: "n"(N) : "memory");
}

// ---------------- fp32 -> bf16 hi/lo split ----------------
__global__ void split_kernel(const float4* __restrict__ src,
                             uint2* __restrict__ hi, uint2* __restrict__ lo, int n4)
{
    int i = blockIdx.x * blockDim.x + threadIdx.x;
    if (i >= n4) return;
    float4 v = src[i];
    uint32_t l0, l1;
    uint32_t h0 = pack_split(v.x, v.y, l0);
    uint32_t h1 = pack_split(v.z, v.w, l1);
    hi[i] = make_uint2(h0, h1);
    lo[i] = make_uint2(l0, l1);
}

// fused 4-way weight split: z selects tensor
struct SplitW {
    const float4 *s0, *s1, *s2, *s3;
    uint2 *h0, *h1, *h2, *h3;
    uint2 *l0, *l1, *l2, *l3;
};
__global__ void split4_kernel(SplitW w, int n4)
{
    int i = blockIdx.x * blockDim.x + threadIdx.x;
    if (i >= n4) return;
    int z = blockIdx.z;
    const float4* src = (z == 0) ? w.s0 : (z == 1) ? w.s1 : (z == 2) ? w.s2 : w.s3;
    uint2* hi = (z == 0) ? w.h0 : (z == 1) ? w.h1 : (z == 2) ? w.h2 : w.h3;
    uint2* lo = (z == 0) ? w.l0 : (z == 1) ? w.l1 : (z == 2) ? w.l2 : w.l3;
    float4 v = src[i];
    uint32_t l0, l1;
    uint32_t h0 = pack_split(v.x, v.y, l0);
    uint32_t h1 = pack_split(v.z, v.w, l1);
    hi[i] = make_uint2(h0, h1);
    lo[i] = make_uint2(l0, l1);
}

// ---------------- per-batch 2048x2048 bf16 transpose (hi+lo fused) ----------
__global__ void transpose_bf16(const __nv_bfloat16* __restrict__ in_h,
                               __nv_bfloat16* __restrict__ out_h,
                               const __nv_bfloat16* __restrict__ in_l,
                               __nv_bfloat16* __restrict__ out_l)
{
    __shared__ __nv_bfloat16 tile[32][33];
    const int bx = blockIdx.x * 32;
    const int by = blockIdx.y * 32;
    const int b  = blockIdx.z & 1;
    const int sel = blockIdx.z >> 1;
    const __nv_bfloat16* in  = sel ? in_l  : in_h;
    __nv_bfloat16*       out = sel ? out_l : out_h;
    const long boff = (long)b * 2048 * 2048;
    const int tx = threadIdx.x & 31;
    const int ty = threadIdx.x >> 5;
#pragma unroll
    for (int j = 0; j < 4; j++) {
        int sl = ty + j*8;
        tile[sl][tx] = in[boff + (long)(by + sl)*2048 + bx + tx];
    }
    __syncthreads();
#pragma unroll
    for (int j = 0; j < 4; j++) {
        int hl = ty + j*8;
        out[boff + (long)(bx + hl)*2048 + by + tx] = tile[tx][hl];
    }
}

// ---------------------------------------------------------------------------
// bf16x3 GEMM, BM=128 x BN=128, 256 threads (8 warps, warp tile 64x32),
// 2-stage cp.async, ldmatrix frags, 2 CTAs/SM. 2.5 B/elem L2 traffic.
// Fused QKV: B/C selected by blockIdx.x>>4.
// ---------------------------------------------------------------------------
#define S_AH 0
#define S_AL 10240
#define S_BH 20480
#define S_BL 30720
#define STG  40960
#define GEMM_SMEM (2*STG)   // 81920 -> 2 CTAs/SM

struct GemmArgs {
    const __nv_bfloat16 *Ah, *Al;
    const __nv_bfloat16 *Bh0, *Bl0, *Bh1, *Bl1, *Bh2, *Bl2;
    float* Cf;
    __nv_bfloat16 *Ch0, *Cl0, *Ch1, *Cl1, *Ch2, *Cl2;
    const float* bias;
};

__device__ __forceinline__ void issue_tile3(uint32_t sb,
    const __nv_bfloat16* __restrict__ Ah, const __nv_bfloat16* __restrict__ Al,
    const __nv_bfloat16* __restrict__ Bh, const __nv_bfloat16* __restrict__ Bl,
    int m0, int n0, int kofs, int tid)
{
#pragma unroll
    for (int i = 0; i < 2; i++) {
        int idx = tid + 256*i;
        int r = idx >> 2, c = idx & 3;
        uint32_t so = r*80 + c*16;
        long ga = (long)(m0 + r)*DMODEL + kofs + c*8;
        long gb = (long)(n0 + r)*DMODEL + kofs + c*8;
        cp16(sb + S_AH + so, Ah + ga);
        cp16(sb + S_AL + so, Al + ga);
        cp16(sb + S_BH + so, Bh + gb);
        cp16(sb + S_BL + so, Bl + gb);
    }
}

template<bool SPLIT_OUT>
__global__ __launch_bounds__(256, 2)
void gemm3(GemmArgs a)
{
    extern __shared__ __align__(16) char gsm[];
    const uint32_t smb = smem_u32(gsm);

    const int tid  = threadIdx.x;
    const int lane = tid & 31;
    const int wid  = tid >> 5;       // 0..7
    const int wm   = wid & 1;        // m-half (64 rows)
    const int wn   = wid >> 1;       // n-quarter (32 cols)
    const int g    = lane >> 2;
    const int t    = lane & 3;
    const int sub  = lane & 7;
    const int sel  = lane >> 3;

    // ldmatrix per-lane offsets (pitch 80B)
    const uint32_t aoff = ((sel & 1)*8 + sub)*80u + (uint32_t)(sel >> 1)*16u;
    const uint32_t boff = ((sel >> 1)*8 + sub)*80u + (uint32_t)(sel & 1)*16u;

    const int bsel = blockIdx.x >> 4;
    const int n0   = (blockIdx.x & 15) * 128;
    const int m0   = blockIdx.y * 128;

    const __nv_bfloat16* Bh = (bsel == 0) ? a.Bh0 : (bsel == 1) ? a.Bh1 : a.Bh2;
    const __nv_bfloat16* Bl = (bsel == 0) ? a.Bl0 : (bsel == 1) ? a.Bl1 : a.Bl2;

    float acc[4][4][4];
#pragma unroll
    for (int mf = 0; mf < 4; mf++)
#pragma unroll
        for (int nf = 0; nf < 4; nf++)
#pragma unroll
            for (int c = 0; c < 4; c++) acc[mf][nf][c] = 0.f;

    const int nk = DMODEL / 32;   // 64

    issue_tile3(smb,       a.Ah, a.Al, Bh, Bl, m0, n0, 0,  tid);
    cp_commit();
    issue_tile3(smb + STG, a.Ah, a.Al, Bh, Bl, m0, n0, 32, tid);
    cp_commit();

    for (int kt = 0; kt < nk; kt++) {
        cp_wait<1>();
        __syncthreads();

        const uint32_t sb32 = smb + (kt & 1)*STG;
        const uint32_t sbAH = sb32 + S_AH + (uint32_t)(wm*64)*80u;
        const uint32_t sbAL = sb32 + S_AL + (uint32_t)(wm*64)*80u;
        const uint32_t sbBH = sb32 + S_BH + (uint32_t)(wn*32)*80u;
        const uint32_t sbBL = sb32 + S_BL + (uint32_t)(wn*32)*80u;

#pragma unroll
        for (int ks = 0; ks < 2; ks++) {
            const uint32_t kb = ks*32;
            uint32_t ah[4][4], bh[4][2], bl[4][2];
#pragma unroll
            for (int mf = 0; mf < 4; mf++)
                ldsm4(ah[mf][0], ah[mf][1], ah[mf][2], ah[mf][3],
                      sbAH + (uint32_t)(mf*16)*80u + kb + aoff);
#pragma unroll
            for (int p = 0; p < 2; p++) {
                ldsm4(bh[2*p][0], bh[2*p][1], bh[2*p+1][0], bh[2*p+1][1],
                      sbBH + (uint32_t)(p*16)*80u + kb + boff);
                ldsm4(bl[2*p][0], bl[2*p][1], bl[2*p+1][0], bl[2*p+1][1],
                      sbBL + (uint32_t)(p*16)*80u + kb + boff);
            }
            // hh pass
#pragma unroll
            for (int mf = 0; mf < 4; mf++)
#pragma unroll
                for (int nf = 0; nf < 4; nf++)
                    mma_bf16(acc[mf][nf], ah[mf], bh[nf]);
            // hl pass
#pragma unroll
            for (int mf = 0; mf < 4; mf++)
#pragma unroll
                for (int nf = 0; nf < 4; nf++)
                    mma_bf16(acc[mf][nf], ah[mf], bl[nf]);
            // load al late (shrinks peak live set), then lh pass
            uint32_t al[4][4];
#pragma unroll
            for (int mf = 0; mf < 4; mf++)
                ldsm4(al[mf][0], al[mf][1], al[mf][2], al[mf][3],
                      sbAL + (uint32_t)(mf*16)*80u + kb + aoff);
#pragma unroll
            for (int mf = 0; mf < 4; mf++)
#pragma unroll
                for (int nf = 0; nf < 4; nf++)
                    mma_bf16(acc[mf][nf], al[mf], bh[nf]);
        }
        __syncthreads();

        if (kt + 2 < nk)
            issue_tile3(smb + (kt & 1)*STG,
                        a.Ah, a.Al, Bh, Bl, m0, n0, (kt+2)*32, tid);
        cp_commit();
    }

    __nv_bfloat16* Ch = (bsel == 0) ? a.Ch0 : (bsel == 1) ? a.Ch1 : a.Ch2;
    __nv_bfloat16* Cl = (bsel == 0) ? a.Cl0 : (bsel == 1) ? a.Cl1 : a.Cl2;

#pragma unroll
    for (int nf = 0; nf < 4; nf++) {
        int col = n0 + wn*32 + nf*8 + 2*t;
        float b0 = 0.f, b1 = 0.f;
        if (!SPLIT_OUT && a.bias) { b0 = a.bias[col]; b1 = a.bias[col + 1]; }
#pragma unroll
        for (int mf = 0; mf < 4; mf++) {
            int row = m0 + wm*64 + mf*16 + g;
            if (SPLIT_OUT) {
                uint32_t l0, l1;
                uint32_t h0 = pack_split(acc[mf][nf][0], acc[mf][nf][1], l0);
                uint32_t h1 = pack_split(acc[mf][nf][2], acc[mf][nf][3], l1);
                *(uint32_t*)(Ch + (long)row*DMODEL + col)     = h0;
                *(uint32_t*)(Cl + (long)row*DMODEL + col)     = l0;
                *(uint32_t*)(Ch + (long)(row+8)*DMODEL + col) = h1;
                *(uint32_t*)(Cl + (long)(row+8)*DMODEL + col) = l1;
            } else {
                *(float2*)(a.Cf + (long)row*DMODEL + col)     = make_float2(acc[mf][nf][0]+b0, acc[mf][nf][1]+b1);
                *(float2*)(a.Cf + (long)(row+8)*DMODEL + col) = make_float2(acc[mf][nf][2]+b0, acc[mf][nf][3]+b1);
            }
        }
    }
}

// ---------------------------------------------------------------------------
// Tensor-core causal flash attention, bf16x3, ldmatrix (unchanged from R11).
// ---------------------------------------------------------------------------
#define AP 136
#define VP 72
#define ATTN_SMEM ((4*64*AP + 2*128*VP)*2)   // 106496 bytes

__global__ __launch_bounds__(128)
void attn_mma(const __nv_bfloat16* __restrict__ Qh, const __nv_bfloat16* __restrict__ Ql,
              const __nv_bfloat16* __restrict__ Kh, const __nv_bfloat16* __restrict__ Kl,
              const __nv_bfloat16* __restrict__ Vth, const __nv_bfloat16* __restrict__ Vtl,
              __nv_bfloat16* __restrict__ Ch, __nv_bfloat16* __restrict__ Cl)
{
    extern __shared__ __nv_bfloat16 sm[];
    __nv_bfloat16* sQh = sm;
    __nv_bfloat16* sQl = sQh + 64*AP;
    __nv_bfloat16* sKh = sQl + 64*AP;
    __nv_bfloat16* sKl = sKh + 64*AP;
    __nv_bfloat16* sVh = sKl + 64*AP;
    __nv_bfloat16* sVl = sVh + 128*VP;

    const uint32_t smb   = smem_u32(sm);
    const uint32_t sQh32 = smb;
    const uint32_t sQl32 = smb + 1*64*AP*2;
    const uint32_t sKh32 = smb + 2*64*AP*2;
    const uint32_t sKl32 = smb + 3*64*AP*2;
    const uint32_t sVh32 = smb + 4*64*AP*2;
    const uint32_t sVl32 = sVh32 + 128*VP*2;

    const int tid  = threadIdx.x;
    const int lane = tid & 31;
    const int wid  = tid >> 5;
    const int g    = lane >> 2;
    const int t    = lane & 3;
    const int sub  = lane & 7;
    const int sel  = lane >> 3;

    const uint32_t qoff = ((sel & 1)*8 + sub)*(AP*2u) + (uint32_t)(sel >> 1)*16u;
    const uint32_t koff = ((sel >> 1)*8 + sub)*(AP*2u) + (uint32_t)(sel & 1)*16u;
    const uint32_t voff = ((sel >> 1)*8 + sub)*(VP*2u) + (uint32_t)(sel & 1)*16u;

    const int qt = gridDim.x - 1 - blockIdx.x;   // LPT ordering
    const int h  = blockIdx.y;
    const int b  = blockIdx.z;
    const int q0 = qt * 64;

    const long qbase = ((long)(b*SEQ + q0))*DMODEL + h*HDIM;
#pragma unroll
    for (int i = 0; i < 8; i++) {
        int u = tid + 128*i;
        int r = u >> 4, c = (u & 15)*8;
        *(uint4*)(sQh + r*AP + c) = *(const uint4*)(Qh + qbase + (long)r*DMODEL + c);
        *(uint4*)(sQl + r*AP + c) = *(const uint4*)(Ql + qbase + (long)r*DMODEL + c);
    }

    float accO[16][4];
#pragma unroll
    for (int nb = 0; nb < 16; nb++)
#pragma unroll
        for (int c = 0; c < 4; c++) accO[nb][c] = 0.f;
    float m2[2] = {-1e30f, -1e30f};
    float lsum[2] = {0.f, 0.f};

    const float SC2 = 0.08838834764831845f * 1.4426950408889634f;
    const long vtbase = ((long)((b*NHEAD + h)*HDIM))*SEQ;

    for (int kt = 0; kt <= qt; kt++) {
        const int k0 = kt * 64;
        const long kbase = ((long)(b*SEQ + k0))*DMODEL + h*HDIM;
#pragma unroll
        for (int i = 0; i < 8; i++) {
            int u = tid + 128*i;
            int r = u >> 4, c = (u & 15)*8;
            *(uint4*)(sKh + r*AP + c) = *(const uint4*)(Kh + kbase + (long)r*DMODEL + c);
            *(uint4*)(sKl + r*AP + c) = *(const uint4*)(Kl + kbase + (long)r*DMODEL + c);
        }
#pragma unroll
        for (int i = 0; i < 8; i++) {
            int u = tid + 128*i;
            int d = u >> 3, c = (u & 7)*8;
            *(uint4*)(sVh + d*VP + c) = *(const uint4*)(Vth + vtbase + (long)d*SEQ + k0 + c);
            *(uint4*)(sVl + d*VP + c) = *(const uint4*)(Vtl + vtbase + (long)d*SEQ + k0 + c);
        }
        __syncthreads();

        float s[8][4];
#pragma unroll
        for (int nb = 0; nb < 8; nb++)
#pragma unroll
            for (int c = 0; c < 4; c++) s[nb][c] = 0.f;

        const uint32_t qbaseb = (uint32_t)(wid*16)*(AP*2u);
#pragma unroll
        for (int kc = 0; kc < 8; kc++) {
            const uint32_t kb = kc*32;
            uint32_t ah[4], al[4];
            ldsm4(ah[0], ah[1], ah[2], ah[3], sQh32 + qbaseb + kb + qoff);
            ldsm4(al[0], al[1], al[2], al[3], sQl32 + qbaseb + kb + qoff);
#pragma unroll
            for (int p = 0; p < 4; p++) {
                uint32_t bh[2][2], bl[2][2];
                ldsm4(bh[0][0], bh[0][1], bh[1][0], bh[1][1],
                      sKh32 + (uint32_t)(p*16)*(AP*2u) + kb + koff);
                ldsm4(bl[0][0], bl[0][1], bl[1][0], bl[1][1],
                      sKl32 + (uint32_t)(p*16)*(AP*2u) + kb + koff);
#pragma unroll
                for (int e = 0; e < 2; e++) {
                    mma_bf16(s[2*p + e], ah, bh[e]);
                    mma_bf16(s[2*p + e], ah, bl[e]);
                    mma_bf16(s[2*p + e], al, bh[e]);
                }
            }
        }

        if (kt == qt) {
            const int r0 = wid*16 + g, r1 = r0 + 8;
#pragma unroll
            for (int nb = 0; nb < 8; nb++) {
                int c0 = nb*8 + 2*t, c1 = c0 + 1;
                if (c0 > r0) s[nb][0] = -1e30f;
                if (c1 > r0) s[nb][1] = -1e30f;
                if (c0 > r1) s[nb][2] = -1e30f;
                if (c1 > r1) s[nb][3] = -1e30f;
            }
        }

        float mx0 = -1e30f, mx1 = -1e30f;
#pragma unroll
        for (int nb = 0; nb < 8; nb++) {
            mx0 = fmaxf(mx0, fmaxf(s[nb][0], s[nb][1]));
            mx1 = fmaxf(mx1, fmaxf(s[nb][2], s[nb][3]));
        }
        mx0 *= SC2; mx1 *= SC2;
#pragma unroll
        for (int off = 1; off <= 2; off <<= 1) {
            mx0 = fmaxf(mx0, __shfl_xor_sync(0xffffffffu, mx0, off));
            mx1 = fmaxf(mx1, __shfl_xor_sync(0xffffffffu, mx1, off));
        }
        float mn0 = fmaxf(m2[0], mx0), mn1 = fmaxf(m2[1], mx1);
        float corr0 = exp2f(m2[0] - mn0), corr1 = exp2f(m2[1] - mn1);
        float sum0 = 0.f, sum1 = 0.f;
#pragma unroll
        for (int nb = 0; nb < 8; nb++) {
            s[nb][0] = exp2f(s[nb][0]*SC2 - mn0);
            s[nb][1] = exp2f(s[nb][1]*SC2 - mn0);
            s[nb][2] = exp2f(s[nb][2]*SC2 - mn1);
            s[nb][3] = exp2f(s[nb][3]*SC2 - mn1);
            sum0 += s[nb][0] + s[nb][1];
            sum1 += s[nb][2] + s[nb][3];
        }
#pragma unroll
        for (int off = 1; off <= 2; off <<= 1) {
            sum0 += __shfl_xor_sync(0xffffffffu, sum0, off);
            sum1 += __shfl_xor_sync(0xffffffffu, sum1, off);
        }
        lsum[0] = lsum[0]*corr0 + sum0;
        lsum[1] = lsum[1]*corr1 + sum1;
        m2[0] = mn0; m2[1] = mn1;
#pragma unroll
        for (int nb = 0; nb < 16; nb++) {
            accO[nb][0] *= corr0; accO[nb][1] *= corr0;
            accO[nb][2] *= corr1; accO[nb][3] *= corr1;
        }

        uint32_t pah[4][4], pal[4][4];
#pragma unroll
        for (int kc = 0; kc < 4; kc++) {
            pah[kc][0] = pack_split(s[2*kc][0],   s[2*kc][1],   pal[kc][0]);
            pah[kc][1] = pack_split(s[2*kc][2],   s[2*kc][3],   pal[kc][1]);
            pah[kc][2] = pack_split(s[2*kc+1][0], s[2*kc+1][1], pal[kc][2]);
            pah[kc][3] = pack_split(s[2*kc+1][2], s[2*kc+1][3], pal[kc][3]);
        }

#pragma unroll
        for (int kc = 0; kc < 4; kc++) {
            const uint32_t kb = kc*32;
#pragma unroll
            for (int p = 0; p < 8; p++) {
                uint32_t vh[2][2], vl[2][2];
                ldsm4(vh[0][0], vh[0][1], vh[1][0], vh[1][1],
                      sVh32 + (uint32_t)(p*16)*(VP*2u) + kb + voff);
                ldsm4(vl[0][0], vl[0][1], vl[1][0], vl[1][1],
                      sVl32 + (uint32_t)(p*16)*(VP*2u) + kb + voff);
#pragma unroll
                for (int e = 0; e < 2; e++) {
                    mma_bf16(accO[2*p + e], pah[kc], vh[e]);
                    mma_bf16(accO[2*p + e], pah[kc], vl[e]);
                    mma_bf16(accO[2*p + e], pal[kc], vh[e]);
                }
            }
        }
        __syncthreads();
    }

    const float inv0 = 1.f / lsum[0], inv1 = 1.f / lsum[1];
    const long obase = ((long)(b*SEQ + q0 + wid*16))*DMODEL + h*HDIM;
#pragma unroll
    for (int nb = 0; nb < 16; nb++) {
        int col = nb*8 + 2*t;
        uint32_t l0, l1;
        uint32_t h0 = pack_split(accO[nb][0]*inv0, accO[nb][1]*inv0, l0);
        uint32_t h1 = pack_split(accO[nb][2]*inv1, accO[nb][3]*inv1, l1);
        *(uint32_t*)(Ch + obase + (long)g*DMODEL + col)     = h0;
        *(uint32_t*)(Cl + obase + (long)g*DMODEL + col)     = l0;
        *(uint32_t*)(Ch + obase + (long)(g+8)*DMODEL + col) = h1;
        *(uint32_t*)(Cl + obase + (long)(g+8)*DMODEL + col) = l1;
    }
}

// ---------------------------------------------------------------------------
// Host launcher
// ---------------------------------------------------------------------------
extern "C" void kernel_launch(void* const* d_in, const int* in_sizes, int n_in,
                              void* d_out, int out_size)
{
    const float* x  = (const float*)d_in[0];
    const float* wq = (const float*)d_in[1];
    const float* wk = (const float*)d_in[2];
    const float* wv = (const float*)d_in[3];
    const float* wo = (const float*)d_in[4];
    const float* bo = (const float*)d_in[5];
    float* out = (float*)d_out;

    __nv_bfloat16 *xs_h, *xs_l, *wqh, *wql, *wkh, *wkl, *wvh, *wvl, *woh, *wol;
    __nv_bfloat16 *qh, *ql, *kh, *kl, *vh, *vl, *vth, *vtl, *ch, *cl;
    cudaGetSymbolAddress((void**)&xs_h, g_xs_h); cudaGetSymbolAddress((void**)&xs_l, g_xs_l);
    cudaGetSymbolAddress((void**)&wqh, g_wq_h);  cudaGetSymbolAddress((void**)&wql, g_wq_l);
    cudaGetSymbolAddress((void**)&wkh, g_wk_h);  cudaGetSymbolAddress((void**)&wkl, g_wk_l);
    cudaGetSymbolAddress((void**)&wvh, g_wv_h);  cudaGetSymbolAddress((void**)&wvl, g_wv_l);
    cudaGetSymbolAddress((void**)&woh, g_wo_h);  cudaGetSymbolAddress((void**)&wol, g_wo_l);
    cudaGetSymbolAddress((void**)&qh, g_q_h);    cudaGetSymbolAddress((void**)&ql, g_q_l);
    cudaGetSymbolAddress((void**)&kh, g_k_h);    cudaGetSymbolAddress((void**)&kl, g_k_l);
    cudaGetSymbolAddress((void**)&vh, g_v_h);    cudaGetSymbolAddress((void**)&vl, g_v_l);
    cudaGetSymbolAddress((void**)&vth, g_vt_h);  cudaGetSymbolAddress((void**)&vtl, g_vt_l);
    cudaGetSymbolAddress((void**)&ch, g_c_h);    cudaGetSymbolAddress((void**)&cl, g_c_l);

    static bool configured = false;
    if (!configured) {
        cudaFuncSetAttribute(gemm3<true>,  cudaFuncAttributeMaxDynamicSharedMemorySize, GEMM_SMEM);
        cudaFuncSetAttribute(gemm3<false>, cudaFuncAttributeMaxDynamicSharedMemorySize, GEMM_SMEM);
        cudaFuncSetAttribute(attn_mma, cudaFuncAttributeMaxDynamicSharedMemorySize, ATTN_SMEM);
        configured = true;
    }

    // 1) split inputs: x + fused 4-weight split
    split_kernel<<<(NTOK/4 + 255)/256, 256>>>((const float4*)x, (uint2*)xs_h, (uint2*)xs_l, NTOK/4);
    {
        SplitW w = {};
        w.s0 = (const float4*)wq; w.s1 = (const float4*)wk;
        w.s2 = (const float4*)wv; w.s3 = (const float4*)wo;
        w.h0 = (uint2*)wqh; w.h1 = (uint2*)wkh; w.h2 = (uint2*)wvh; w.h3 = (uint2*)woh;
        w.l0 = (uint2*)wql; w.l1 = (uint2*)wkl; w.l2 = (uint2*)wvl; w.l3 = (uint2*)wol;
        split4_kernel<<<dim3((NW/4 + 255)/256, 1, 4), 256>>>(w, NW/4);
    }

    // 2) fused QKV projection: grid (48, 32)
    {
        GemmArgs a = {};
        a.Ah = xs_h; a.Al = xs_l;
        a.Bh0 = wqh; a.Bl0 = wql; a.Bh1 = wkh; a.Bl1 = wkl; a.Bh2 = wvh; a.Bl2 = wvl;
        a.Ch0 = qh;  a.Cl0 = ql;  a.Ch1 = kh;  a.Cl1 = kl;  a.Ch2 = vh;  a.Cl2 = vl;
        gemm3<true><<<dim3(48, MTOT/128), 256, GEMM_SMEM>>>(a);
    }

    // 3) V transpose, hi and lo fused
    transpose_bf16<<<dim3(64, 64, 2*BATCH), 256>>>(vh, vth, vl, vtl);

    // 4) attention
    attn_mma<<<dim3(SEQ/64, NHEAD, BATCH), 128, ATTN_SMEM>>>(qh, ql, kh, kl, vth, vtl, ch, cl);

    // 5) output projection (fp32 + bias), grid (16, 32)
    {
        GemmArgs a = {};
        a.Ah = ch; a.Al = cl;
        a.Bh0 = woh; a.Bl0 = wol; a.Bh1 = woh; a.Bl1 = wol; a.Bh2 = woh; a.Bl2 = wol;
        a.Cf = out; a.bias = bo;
        gemm3<false><<<dim3(16, MTOT/128), 256, GEMM_SMEM>>>(a);
    }
}